// round 9
// baseline (speedup 1.0000x reference)
#include <cuda_runtime.h>
#include <math.h>
#include <stdint.h>

// ---------------- problem constants ----------------
#define BQ 4
#define LQ 1024
#define DMQ 512
#define DIQ 1024
#define NHQ 16
#define HDQ 64
#define NSQ 16
#define DCONVQ 4
#define CONV_DIMQ 1056
#define DPROJQ 2096
#define DFFQ 2048
#define NLAYERSQ 6
#define BLQ (BQ*LQ)          // 4096 rows
#define EPSQ 1e-5f

// GEMM tiling
#define BN 128
#define BK 32
#define LDK 36               // padded k-stride (floats); 144B = 9*16B -> ldmatrix-aligned, conflict-free

// scan chunking
#define NCHUNK 32
#define CLEN (LQ/NCHUNK)     // 32

// ---------------- scratch (device globals, no allocation) ----------------
__device__ float g_x  [BLQ*DMQ];
__device__ float g_xn [BLQ*DMQ];
__device__ float g_zx [BLQ*DPROJQ];
__device__ float g_bc [BLQ*2*NSQ];       // conv+silu'd B,C (compact)
__device__ float g_y  [BLQ*DIQ];
__device__ float g_h1 [BLQ*DFFQ];
__device__ float g_hfin [BQ*NHQ*NCHUNK*HDQ*NSQ];
__device__ float g_hinit[BQ*NHQ*NCHUNK*HDQ*NSQ];
__device__ float g_cuma [BLQ*NHQ];
__device__ float g_P    [BQ*NHQ*NCHUNK];
__device__ float g_wip[NLAYERSQ*DPROJQ*DMQ];
__device__ float g_wop[NLAYERSQ*DMQ*DIQ];
__device__ float g_w1 [NLAYERSQ*DFFQ*DMQ];
__device__ float g_w2 [NLAYERSQ*DMQ*DFFQ];

// ---------------- helpers ----------------
__device__ __forceinline__ float block_reduce_sum(float v, float* sh) {
    int lane = threadIdx.x & 31, wid = threadIdx.x >> 5;
    #pragma unroll
    for (int o = 16; o; o >>= 1) v += __shfl_xor_sync(0xFFFFFFFFu, v, o);
    if (lane == 0) sh[wid] = v;
    __syncthreads();
    int nw = blockDim.x >> 5;
    v = (threadIdx.x < nw) ? sh[threadIdx.x] : 0.f;
    if (wid == 0) {
        #pragma unroll
        for (int o = 16; o; o >>= 1) v += __shfl_xor_sync(0xFFFFFFFFu, v, o);
        if (lane == 0) sh[0] = v;
    }
    __syncthreads();
    float r = sh[0];
    __syncthreads();
    return r;
}

__device__ __forceinline__ uint32_t f2tf32(float f) {
    uint32_t u;
    asm("cvt.rna.tf32.f32 %0, %1;" : "=r"(u) : "f"(f));
    return u;
}
__device__ __forceinline__ float rnd_tf32(float f) { return __uint_as_float(f2tf32(f)); }

__device__ __forceinline__ void cp16(uint32_t dst, const void* src, bool pred) {
    int sz = pred ? 16 : 0;
    asm volatile("cp.async.cg.shared.global [%0], [%1], 16, %2;\n"
                 :: "r"(dst), "l"(src), "r"(sz) : "memory");
}
__device__ __forceinline__ void cp_commit() {
    asm volatile("cp.async.commit_group;\n" ::: "memory");
}

__device__ __forceinline__ void ldsm4(uint32_t& r0, uint32_t& r1, uint32_t& r2, uint32_t& r3,
                                      uint32_t addr) {
    asm volatile("ldmatrix.sync.aligned.m8n8.x4.shared.b16 {%0,%1,%2,%3}, [%4];"
                 : "=r"(r0), "=r"(r1), "=r"(r2), "=r"(r3) : "r"(addr));
}

// fused 4-tensor tf32 rounding (grid-stride per segment)
__global__ void cvt4_tf32_kernel(const float* __restrict__ i0, float* __restrict__ o0, int n0,
                                 const float* __restrict__ i1, float* __restrict__ o1, int n1,
                                 const float* __restrict__ i2, float* __restrict__ o2, int n2,
                                 const float* __restrict__ i3, float* __restrict__ o3, int n3) {
    int stride4 = gridDim.x * blockDim.x * 4;
    int base = (blockIdx.x * blockDim.x + threadIdx.x) * 4;
    #pragma unroll
    for (int seg = 0; seg < 4; seg++) {
        const float* in  = (seg==0) ? i0 : (seg==1) ? i1 : (seg==2) ? i2 : i3;
        float* out       = (seg==0) ? o0 : (seg==1) ? o1 : (seg==2) ? o2 : o3;
        int n            = (seg==0) ? n0 : (seg==1) ? n1 : (seg==2) ? n2 : n3;
        for (int i = base; i < n; i += stride4) {
            float4 v = *(const float4*)&in[i];
            v.x = rnd_tf32(v.x); v.y = rnd_tf32(v.y);
            v.z = rnd_tf32(v.z); v.w = rnd_tf32(v.w);
            *(float4*)&out[i] = v;
        }
    }
}

// ---------------- rmsnorm over DM=512 ----------------
template<int COPY>
__global__ void rmsnorm_kernel(const float* __restrict__ in, const float* __restrict__ w,
                               float* __restrict__ out, float* __restrict__ xcopy,
                               int round_out) {
    __shared__ float sh[32];
    int m = blockIdx.x;
    int t = threadIdx.x;
    const float* row = in + (size_t)m * DMQ;
    float v[4]; float ss = 0.f;
    #pragma unroll
    for (int i = 0; i < 4; i++) { v[i] = row[t + i*128]; ss += v[i]*v[i]; }
    float tot = block_reduce_sum(ss, sh);
    float scale = rsqrtf(tot * (1.f/DMQ) + EPSQ);
    float* orow = out + (size_t)m * DMQ;
    #pragma unroll
    for (int i = 0; i < 4; i++) {
        float o = v[i] * scale * w[t + i*128];
        orow[t + i*128] = round_out ? rnd_tf32(o) : o;
        if (COPY) xcopy[(size_t)m * DMQ + t + i*128] = v[i];
    }
}

// ---------------- tensor-core GEMM (R5 best config) ----------------
template<int EPI, int BMt>
__global__ void __launch_bounds__(128, (BMt==128) ? 2 : 3)
gemm_tc4(const float* __restrict__ A, const float* __restrict__ W,
         float* __restrict__ C, const float* __restrict__ bias,
         const float* __restrict__ resid, int M, int N, int K) {
    constexpr int MT = BMt / 32;
    extern __shared__ float sm[];
    float* As = sm;                        // [2][BMt][LDK]
    float* Bs = sm + 2 * BMt * LDK;        // [2][BN][LDK]

    int tid  = threadIdx.x;
    int warp = tid >> 5, lane = tid & 31;
    int wm = warp & 1;
    int wn = warp >> 1;

    int m0 = blockIdx.y * BMt;
    int n0 = blockIdx.x * BN;

    float acc[MT][8][4];
    #pragma unroll
    for (int i = 0; i < MT; i++)
        #pragma unroll
        for (int j = 0; j < 8; j++)
            #pragma unroll
            for (int c = 0; c < 4; c++) acc[i][j][c] = 0.f;

    auto stage = [&](int buf, int k0) {
        float* Ab = As + buf * BMt * LDK;
        #pragma unroll
        for (int it = 0; it < (BMt*8)/128; it++) {
            int ch = it * 128 + tid;
            int r = ch >> 3, kc = (ch & 7) * 4;
            uint32_t dst = (uint32_t)__cvta_generic_to_shared(&Ab[r * LDK + kc]);
            cp16(dst, &A[(size_t)(m0 + r) * K + k0 + kc], true);
        }
        float* Bb = Bs + buf * BN * LDK;
        #pragma unroll
        for (int it = 0; it < 8; it++) {
            int ch = it * 128 + tid;
            int r = ch >> 3, kc = (ch & 7) * 4;
            int n = n0 + r;
            bool ok = (n < N);
            uint32_t dst = (uint32_t)__cvta_generic_to_shared(&Bb[r * LDK + kc]);
            cp16(dst, &W[(size_t)(ok ? n : 0) * K + k0 + kc], ok);
        }
        cp_commit();
    };

    uint32_t aRow = (uint32_t)(wm * (BMt/2) + (lane & 15));
    uint32_t aColB = (lane >> 4) * 16;
    uint32_t aBaseOff = (aRow * LDK) * 4 + aColB;
    uint32_t bRow = (uint32_t)(wn * 64 + (lane & 7) + ((lane & 16) >> 1));
    uint32_t bColB = (lane & 8) * 2;
    uint32_t bBaseOff = (bRow * LDK) * 4 + bColB;

    int ntiles = K / BK;
    stage(0, 0);
    for (int i = 0; i < ntiles; i++) {
        if (i + 1 < ntiles) {
            stage((i + 1) & 1, (i + 1) * BK);
            asm volatile("cp.async.wait_group 1;\n" ::: "memory");
        } else {
            asm volatile("cp.async.wait_group 0;\n" ::: "memory");
        }
        __syncthreads();

        uint32_t sAb = (uint32_t)__cvta_generic_to_shared(As + (i & 1) * BMt * LDK);
        uint32_t sBb = (uint32_t)__cvta_generic_to_shared(Bs + (i & 1) * BN * LDK);
        uint32_t aAddr = sAb + aBaseOff;
        uint32_t bAddr = sBb + bBaseOff;

        #pragma unroll
        for (int kk = 0; kk < BK; kk += 8) {
            uint32_t af[MT][4];
            #pragma unroll
            for (int mt = 0; mt < MT; mt++)
                ldsm4(af[mt][0], af[mt][1], af[mt][2], af[mt][3],
                      aAddr + (uint32_t)(mt * 16 * LDK + kk) * 4);
            uint32_t bf[8][2];
            #pragma unroll
            for (int ntp = 0; ntp < 4; ntp++)
                ldsm4(bf[2*ntp][0], bf[2*ntp][1], bf[2*ntp+1][0], bf[2*ntp+1][1],
                      bAddr + (uint32_t)(ntp * 16 * LDK + kk) * 4);
            #pragma unroll
            for (int mt = 0; mt < MT; mt++)
                #pragma unroll
                for (int nt = 0; nt < 8; nt++) {
                    asm volatile(
                        "mma.sync.aligned.m16n8k8.row.col.f32.tf32.tf32.f32 "
                        "{%0,%1,%2,%3}, {%4,%5,%6,%7}, {%8,%9}, {%0,%1,%2,%3};"
                        : "+f"(acc[mt][nt][0]), "+f"(acc[mt][nt][1]),
                          "+f"(acc[mt][nt][2]), "+f"(acc[mt][nt][3])
                        : "r"(af[mt][0]), "r"(af[mt][1]), "r"(af[mt][2]), "r"(af[mt][3]),
                          "r"(bf[nt][0]), "r"(bf[nt][1]));
                }
        }
        __syncthreads();
    }

    int gg = lane >> 2, tt = lane & 3;
    #pragma unroll
    for (int mt = 0; mt < MT; mt++) {
        #pragma unroll
        for (int nt = 0; nt < 8; nt++) {
            int mbase = m0 + wm * (BMt/2) + mt * 16 + gg;
            int nn = n0 + wn * 64 + nt * 8 + 2 * tt;
            if (nn < N) {
                #pragma unroll
                for (int rhalf = 0; rhalf < 2; rhalf++) {
                    int mm = mbase + rhalf * 8;
                    float v0 = acc[mt][nt][rhalf*2 + 0];
                    float v1 = acc[mt][nt][rhalf*2 + 1];
                    if (EPI == 1) {
                        v0 += bias[nn];     v1 += bias[nn+1];
                        v0 = 0.5f * v0 * (1.f + erff(v0 * 0.70710678118654752f));
                        v1 = 0.5f * v1 * (1.f + erff(v1 * 0.70710678118654752f));
                        v0 = rnd_tf32(v0);  v1 = rnd_tf32(v1);
                    } else if (EPI == 2) {
                        float2 r = *(const float2*)&resid[(size_t)mm * N + nn];
                        v0 += r.x; v1 += r.y;
                    } else if (EPI == 3) {
                        float2 r = *(const float2*)&resid[(size_t)mm * N + nn];
                        v0 += bias[nn] + r.x; v1 += bias[nn+1] + r.y;
                    }
                    *(float2*)&C[(size_t)mm * N + nn] = make_float2(v0, v1);
                }
            }
        }
    }
}

// ---------------- chunked scan pass 1: fused conv(k=4)+silu + dt/dA + local scan ----------------
__global__ void scan1_kernel(const float* __restrict__ zx, const float* __restrict__ cw,
                             const float* __restrict__ cb,
                             const float* __restrict__ dtb, const float* __restrict__ Alog,
                             const float* __restrict__ D_ssm,
                             float* __restrict__ y, float* __restrict__ bcout,
                             float* __restrict__ hfin,
                             float* __restrict__ cuma, float* __restrict__ P) {
    int blk = blockIdx.x;
    int c = blk % NCHUNK;
    int bh = blk / NCHUNK;
    int h = bh % NHQ, b = bh / NHQ;
    int p = threadIdx.x;
    int lane = p & 31;

    int chx  = h * HDQ + p;
    int chbc = DIQ + lane;
    int colx  = DIQ + chx;
    int colbc = DIQ + chbc;

    float cwx[DCONVQ], cwb[DCONVQ];
    #pragma unroll
    for (int j = 0; j < DCONVQ; j++) {
        cwx[j] = cw[chx*DCONVQ + j];
        cwb[j] = cw[chbc*DCONVQ + j];
    }
    float cbx = cb[chx], cbb = cb[chbc];

    float Dh = D_ssm[h];
    float dtbh = dtb[h];
    float eA = expf(Alog[h]);

    int l0 = c * CLEN;
    size_t rowbase = (size_t)b * LQ;

    float xw0=0.f, xw1=0.f, xw2=0.f, bw0=0.f, bw1=0.f, bw2=0.f;
    {
        int ll = l0 - 3;
        if (ll >= 0) { size_t r = rowbase + ll; xw0 = zx[r*DPROJQ + colx]; bw0 = zx[r*DPROJQ + colbc]; }
        ll = l0 - 2;
        if (ll >= 0) { size_t r = rowbase + ll; xw1 = zx[r*DPROJQ + colx]; bw1 = zx[r*DPROJQ + colbc]; }
        ll = l0 - 1;
        if (ll >= 0) { size_t r = rowbase + ll; xw2 = zx[r*DPROJQ + colx]; bw2 = zx[r*DPROJQ + colbc]; }
    }

    float hs[NSQ];
    #pragma unroll
    for (int n = 0; n < NSQ; n++) hs[n] = 0.f;
    float cum = 1.f;

    for (int l = l0; l < l0 + CLEN; l++) {
        size_t row = rowbase + l;
        float xn = zx[row*DPROJQ + colx];
        float bn = zx[row*DPROJQ + colbc];
        float accx = cbx;
        accx = fmaf(xw0, cwx[0], accx);
        accx = fmaf(xw1, cwx[1], accx);
        accx = fmaf(xw2, cwx[2], accx);
        accx = fmaf(xn,  cwx[3], accx);
        float accb = cbb;
        accb = fmaf(bw0, cwb[0], accb);
        accb = fmaf(bw1, cwb[1], accb);
        accb = fmaf(bw2, cwb[2], accb);
        accb = fmaf(bn,  cwb[3], accb);
        xw0 = xw1; xw1 = xw2; xw2 = xn;
        bw0 = bw1; bw1 = bw2; bw2 = bn;

        float xv  = accx / (1.f + expf(-accx));
        float bcv = accb / (1.f + expf(-accb));
        if (h == 0 && p < 32) bcout[row*(2*NSQ) + lane] = bcv;

        float raw = zx[row*DPROJQ + (DPROJQ - NHQ) + h] + dtbh;
        float dtv = (raw > 20.f) ? raw : log1pf(expf(raw));
        float a   = expf(-eA * dtv);
        cum *= a;
        if (p == 0) cuma[row*NHQ + h] = cum;

        float coef = dtv * xv;
        float acc = 0.f;
        #pragma unroll
        for (int n = 0; n < NSQ; n++) {
            float Bn = __shfl_sync(0xFFFFFFFFu, bcv, n);
            float Cn = __shfl_sync(0xFFFFFFFFu, bcv, 16 + n);
            hs[n] = fmaf(hs[n], a, coef * Bn);
            acc = fmaf(hs[n], Cn, acc);
        }
        y[row*DIQ + h*HDQ + p] = acc + Dh * xv;
    }
    size_t base = ((size_t)blk * HDQ + p) * NSQ;
    #pragma unroll
    for (int n = 0; n < NSQ; n++) hfin[base + n] = hs[n];
    if (p == 0) P[blk] = cum;
}

// ---------------- chunked scan pass 2 (widened: 4 blocks per bh) ----------------
__global__ void scan2_kernel(const float* __restrict__ hfin, const float* __restrict__ P,
                             float* __restrict__ hinit) {
    int bh = blockIdx.x >> 2;
    int e  = (blockIdx.x & 3) * 256 + threadIdx.x;
    float cur = 0.f;
    #pragma unroll 4
    for (int cc = 0; cc < NCHUNK; cc++) {
        size_t idx = (size_t)(bh * NCHUNK + cc) * (HDQ*NSQ) + e;
        hinit[idx] = cur;
        cur = P[bh * NCHUNK + cc] * cur + hfin[idx];
    }
}

// ---------------- fused scan pass 3 + gated RMSNorm ----------------
// grid = BQ*NCHUNK blocks, 1024 threads (one per DI channel -> whole row in block)
__global__ void scan3_gate_kernel(const float* __restrict__ bc, const float* __restrict__ cuma,
                                  const float* __restrict__ hinit, const float* __restrict__ zx,
                                  const float* __restrict__ gw, float* __restrict__ y) {
    __shared__ float sh[32];
    __shared__ float sC[NSQ];
    __shared__ float sca[NHQ];

    int blk = blockIdx.x;
    int c = blk % NCHUNK;
    int b = blk / NCHUNK;
    int ch = threadIdx.x;            // 0..1023
    int h = ch >> 6, p = ch & 63;
    int bh = b * NHQ + h;

    float hi[NSQ];
    if (c > 0) {
        size_t base = ((size_t)(bh * NCHUNK + c) * HDQ + p) * NSQ;
        #pragma unroll
        for (int n = 0; n < NSQ; n++) hi[n] = hinit[base + n];
    } else {
        #pragma unroll
        for (int n = 0; n < NSQ; n++) hi[n] = 0.f;
    }
    float gwc = gw[ch];

    int l0 = c * CLEN;
    for (int l = l0; l < l0 + CLEN; l++) {
        size_t row = (size_t)b * LQ + l;
        if (ch < NSQ) sC[ch] = bc[row*(2*NSQ) + NSQ + ch];
        else if (ch >= 32 && ch < 32 + NHQ) sca[ch - 32] = cuma[row*NHQ + (ch - 32)];
        __syncthreads();

        float yy = y[row*DIQ + ch];
        if (c > 0) {
            float corr = 0.f;
            #pragma unroll
            for (int n = 0; n < NSQ; n++)
                corr = fmaf(hi[n], sC[n], corr);
            yy += sca[h] * corr;
        }
        float z = zx[row*DPROJQ + ch];
        float g = z / (1.f + expf(-z));
        float v = yy * g;
        float tot = block_reduce_sum(v * v, sh);   // contains syncthreads (protects sC reuse)
        float scale = rsqrtf(tot * (1.f/DIQ) + EPSQ);
        y[row*DIQ + ch] = rnd_tf32(v * scale * gwc);
    }
}

// ---------------- launcher ----------------
extern "C" void kernel_launch(void* const* d_in, const int* in_sizes, int n_in,
                              void* d_out, int out_size) {
    const float* x          = (const float*)d_in[0];
    const float* in_proj_w  = (const float*)d_in[1];
    const float* conv_w     = (const float*)d_in[2];
    const float* conv_b     = (const float*)d_in[3];
    const float* dt_bias    = (const float*)d_in[4];
    const float* A_log      = (const float*)d_in[5];
    const float* D_ssm      = (const float*)d_in[6];
    const float* gnorm_w    = (const float*)d_in[7];
    const float* out_proj_w = (const float*)d_in[8];
    const float* ffn_w1     = (const float*)d_in[9];
    const float* ffn_b1     = (const float*)d_in[10];
    const float* ffn_w2     = (const float*)d_in[11];
    const float* ffn_b2     = (const float*)d_in[12];
    const float* norm_mamba = (const float*)d_in[13];
    const float* norm_ffn   = (const float*)d_in[14];
    const float* final_norm = (const float*)d_in[15];
    float* out = (float*)d_out;

    float *gx, *gxn, *gzx, *gbc, *gy, *gh1;
    float *ghfin, *ghinit, *gcuma, *gP, *gwip, *gwop, *gw1, *gw2;
    cudaGetSymbolAddress((void**)&gx,  g_x);
    cudaGetSymbolAddress((void**)&gxn, g_xn);
    cudaGetSymbolAddress((void**)&gzx, g_zx);
    cudaGetSymbolAddress((void**)&gbc, g_bc);
    cudaGetSymbolAddress((void**)&gy,  g_y);
    cudaGetSymbolAddress((void**)&gh1, g_h1);
    cudaGetSymbolAddress((void**)&ghfin, g_hfin);
    cudaGetSymbolAddress((void**)&ghinit,g_hinit);
    cudaGetSymbolAddress((void**)&gcuma, g_cuma);
    cudaGetSymbolAddress((void**)&gP,    g_P);
    cudaGetSymbolAddress((void**)&gwip,  g_wip);
    cudaGetSymbolAddress((void**)&gwop,  g_wop);
    cudaGetSymbolAddress((void**)&gw1,   g_w1);
    cudaGetSymbolAddress((void**)&gw2,   g_w2);

    const int smem128 = (2*128*LDK + 2*BN*LDK) * 4;
    const int smem64  = (2*64 *LDK + 2*BN*LDK) * 4;
    cudaFuncSetAttribute(gemm_tc4<0,128>, cudaFuncAttributeMaxDynamicSharedMemorySize, smem128);
    cudaFuncSetAttribute(gemm_tc4<1,128>, cudaFuncAttributeMaxDynamicSharedMemorySize, smem128);
    cudaFuncSetAttribute(gemm_tc4<2,64>,  cudaFuncAttributeMaxDynamicSharedMemorySize, smem64);
    cudaFuncSetAttribute(gemm_tc4<3,64>,  cudaFuncAttributeMaxDynamicSharedMemorySize, smem64);

    // pre-round all weights to tf32 bit patterns (one fused launch)
    cvt4_tf32_kernel<<<2048, 256>>>(
        in_proj_w,  gwip, NLAYERSQ*DPROJQ*DMQ,
        out_proj_w, gwop, NLAYERSQ*DMQ*DIQ,
        ffn_w1,     gw1,  NLAYERSQ*DFFQ*DMQ,
        ffn_w2,     gw2,  NLAYERSQ*DMQ*DFFQ);

    for (int i = 0; i < NLAYERSQ; i++) {
        // --- mamba block ---
        if (i == 0) {
            rmsnorm_kernel<1><<<BLQ, 128>>>(x, norm_mamba, gxn, gx, 1);
        } else {
            rmsnorm_kernel<0><<<BLQ, 128>>>(gx, norm_mamba + i*DMQ, gxn, nullptr, 1);
        }

        gemm_tc4<0,128><<<dim3((DPROJQ+BN-1)/BN, BLQ/128), 128, smem128>>>(
            gxn, gwip + (size_t)i*DPROJQ*DMQ, gzx, nullptr, nullptr,
            BLQ, DPROJQ, DMQ);

        scan1_kernel<<<BQ*NHQ*NCHUNK, HDQ>>>(
            gzx, conv_w + (size_t)i*CONV_DIMQ*DCONVQ, conv_b + (size_t)i*CONV_DIMQ,
            dt_bias + i*NHQ, A_log + i*NHQ, D_ssm + i*NHQ,
            gy, gbc, ghfin, gcuma, gP);
        scan2_kernel<<<BQ*NHQ*4, 256>>>(ghfin, gP, ghinit);
        scan3_gate_kernel<<<BQ*NCHUNK, 1024>>>(gbc, gcuma, ghinit, gzx,
                                               gnorm_w + (size_t)i*DIQ, gy);

        gemm_tc4<2,64><<<dim3(DMQ/BN, BLQ/64), 128, smem64>>>(
            gy, gwop + (size_t)i*DMQ*DIQ, gx, nullptr, gx,
            BLQ, DMQ, DIQ);

        // --- ffn block ---
        rmsnorm_kernel<0><<<BLQ, 128>>>(gx, norm_ffn + i*DMQ, gxn, nullptr, 1);

        gemm_tc4<1,128><<<dim3(DFFQ/BN, BLQ/128), 128, smem128>>>(
            gxn, gw1 + (size_t)i*DFFQ*DMQ, gh1, ffn_b1 + (size_t)i*DFFQ, nullptr,
            BLQ, DFFQ, DMQ);

        gemm_tc4<3,64><<<dim3(DMQ/BN, BLQ/64), 128, smem64>>>(
            gh1, gw2 + (size_t)i*DMQ*DFFQ, gx, ffn_b2 + (size_t)i*DMQ, gx,
            BLQ, DMQ, DFFQ);
    }

    rmsnorm_kernel<0><<<BLQ, 128>>>(gx, final_norm, out, nullptr, 0);
}

// round 11
// speedup vs baseline: 1.0648x; 1.0648x over previous
#include <cuda_runtime.h>
#include <math.h>
#include <stdint.h>

// ---------------- problem constants ----------------
#define BQ 4
#define LQ 1024
#define DMQ 512
#define DIQ 1024
#define NHQ 16
#define HDQ 64
#define NSQ 16
#define DCONVQ 4
#define CONV_DIMQ 1056
#define DPROJQ 2096
#define DFFQ 2048
#define NLAYERSQ 6
#define BLQ (BQ*LQ)          // 4096 rows
#define EPSQ 1e-5f

// GEMM tiling
#define BN 128
#define BK 32
#define LDK 36               // padded k-stride (floats); 144B = 9*16B -> ldmatrix-aligned, conflict-free

// scan chunking
#define NCHUNK 64
#define CLEN (LQ/NCHUNK)     // 16

// ---------------- scratch (device globals, no allocation) ----------------
__device__ float g_x  [BLQ*DMQ];
__device__ float g_xn [BLQ*DMQ];
__device__ float g_zx [BLQ*DPROJQ];
__device__ float g_bc [BLQ*2*NSQ];       // conv+silu'd B,C (compact)
__device__ float g_y  [BLQ*DIQ];
__device__ float g_h1 [BLQ*DFFQ];
__device__ float g_hfin [BQ*NHQ*NCHUNK*HDQ*NSQ];
__device__ float g_hinit[BQ*NHQ*NCHUNK*HDQ*NSQ];
__device__ float g_cuma [BLQ*NHQ];
__device__ float g_P    [BQ*NHQ*NCHUNK];
__device__ float g_wip[NLAYERSQ*DPROJQ*DMQ];
__device__ float g_wop[NLAYERSQ*DMQ*DIQ];
__device__ float g_w1 [NLAYERSQ*DFFQ*DMQ];
__device__ float g_w2 [NLAYERSQ*DMQ*DFFQ];

// ---------------- helpers ----------------
__device__ __forceinline__ float block_reduce_sum(float v, float* sh) {
    int lane = threadIdx.x & 31, wid = threadIdx.x >> 5;
    #pragma unroll
    for (int o = 16; o; o >>= 1) v += __shfl_xor_sync(0xFFFFFFFFu, v, o);
    if (lane == 0) sh[wid] = v;
    __syncthreads();
    int nw = blockDim.x >> 5;
    v = (threadIdx.x < nw) ? sh[threadIdx.x] : 0.f;
    if (wid == 0) {
        #pragma unroll
        for (int o = 16; o; o >>= 1) v += __shfl_xor_sync(0xFFFFFFFFu, v, o);
        if (lane == 0) sh[0] = v;
    }
    __syncthreads();
    float r = sh[0];
    __syncthreads();
    return r;
}

__device__ __forceinline__ uint32_t f2tf32(float f) {
    uint32_t u;
    asm("cvt.rna.tf32.f32 %0, %1;" : "=r"(u) : "f"(f));
    return u;
}
__device__ __forceinline__ float rnd_tf32(float f) { return __uint_as_float(f2tf32(f)); }

__device__ __forceinline__ void cp16(uint32_t dst, const void* src, bool pred) {
    int sz = pred ? 16 : 0;
    asm volatile("cp.async.cg.shared.global [%0], [%1], 16, %2;\n"
                 :: "r"(dst), "l"(src), "r"(sz) : "memory");
}
__device__ __forceinline__ void cp_commit() {
    asm volatile("cp.async.commit_group;\n" ::: "memory");
}

__device__ __forceinline__ void ldsm4(uint32_t& r0, uint32_t& r1, uint32_t& r2, uint32_t& r3,
                                      uint32_t addr) {
    asm volatile("ldmatrix.sync.aligned.m8n8.x4.shared.b16 {%0,%1,%2,%3}, [%4];"
                 : "=r"(r0), "=r"(r1), "=r"(r2), "=r"(r3) : "r"(addr));
}

// fused 4-tensor tf32 rounding (grid-stride per segment)
__global__ void cvt4_tf32_kernel(const float* __restrict__ i0, float* __restrict__ o0, int n0,
                                 const float* __restrict__ i1, float* __restrict__ o1, int n1,
                                 const float* __restrict__ i2, float* __restrict__ o2, int n2,
                                 const float* __restrict__ i3, float* __restrict__ o3, int n3) {
    int stride4 = gridDim.x * blockDim.x * 4;
    int base = (blockIdx.x * blockDim.x + threadIdx.x) * 4;
    #pragma unroll
    for (int seg = 0; seg < 4; seg++) {
        const float* in  = (seg==0) ? i0 : (seg==1) ? i1 : (seg==2) ? i2 : i3;
        float* out       = (seg==0) ? o0 : (seg==1) ? o1 : (seg==2) ? o2 : o3;
        int n            = (seg==0) ? n0 : (seg==1) ? n1 : (seg==2) ? n2 : n3;
        for (int i = base; i < n; i += stride4) {
            float4 v = *(const float4*)&in[i];
            v.x = rnd_tf32(v.x); v.y = rnd_tf32(v.y);
            v.z = rnd_tf32(v.z); v.w = rnd_tf32(v.w);
            *(float4*)&out[i] = v;
        }
    }
}

// ---------------- rmsnorm over DM=512 ----------------
template<int COPY>
__global__ void rmsnorm_kernel(const float* __restrict__ in, const float* __restrict__ w,
                               float* __restrict__ out, float* __restrict__ xcopy,
                               int round_out) {
    __shared__ float sh[32];
    int m = blockIdx.x;
    int t = threadIdx.x;
    const float* row = in + (size_t)m * DMQ;
    float v[4]; float ss = 0.f;
    #pragma unroll
    for (int i = 0; i < 4; i++) { v[i] = row[t + i*128]; ss += v[i]*v[i]; }
    float tot = block_reduce_sum(ss, sh);
    float scale = rsqrtf(tot * (1.f/DMQ) + EPSQ);
    float* orow = out + (size_t)m * DMQ;
    #pragma unroll
    for (int i = 0; i < 4; i++) {
        float o = v[i] * scale * w[t + i*128];
        orow[t + i*128] = round_out ? rnd_tf32(o) : o;
        if (COPY) xcopy[(size_t)m * DMQ + t + i*128] = v[i];
    }
}

// ---------------- tensor-core GEMM (R5 best config) ----------------
template<int EPI, int BMt>
__global__ void __launch_bounds__(128, (BMt==128) ? 2 : 3)
gemm_tc4(const float* __restrict__ A, const float* __restrict__ W,
         float* __restrict__ C, const float* __restrict__ bias,
         const float* __restrict__ resid, int M, int N, int K) {
    constexpr int MT = BMt / 32;
    extern __shared__ float sm[];
    float* As = sm;                        // [2][BMt][LDK]
    float* Bs = sm + 2 * BMt * LDK;        // [2][BN][LDK]

    int tid  = threadIdx.x;
    int warp = tid >> 5, lane = tid & 31;
    int wm = warp & 1;
    int wn = warp >> 1;

    int m0 = blockIdx.y * BMt;
    int n0 = blockIdx.x * BN;

    float acc[MT][8][4];
    #pragma unroll
    for (int i = 0; i < MT; i++)
        #pragma unroll
        for (int j = 0; j < 8; j++)
            #pragma unroll
            for (int c = 0; c < 4; c++) acc[i][j][c] = 0.f;

    auto stage = [&](int buf, int k0) {
        float* Ab = As + buf * BMt * LDK;
        #pragma unroll
        for (int it = 0; it < (BMt*8)/128; it++) {
            int ch = it * 128 + tid;
            int r = ch >> 3, kc = (ch & 7) * 4;
            uint32_t dst = (uint32_t)__cvta_generic_to_shared(&Ab[r * LDK + kc]);
            cp16(dst, &A[(size_t)(m0 + r) * K + k0 + kc], true);
        }
        float* Bb = Bs + buf * BN * LDK;
        #pragma unroll
        for (int it = 0; it < 8; it++) {
            int ch = it * 128 + tid;
            int r = ch >> 3, kc = (ch & 7) * 4;
            int n = n0 + r;
            bool ok = (n < N);
            uint32_t dst = (uint32_t)__cvta_generic_to_shared(&Bb[r * LDK + kc]);
            cp16(dst, &W[(size_t)(ok ? n : 0) * K + k0 + kc], ok);
        }
        cp_commit();
    };

    uint32_t aRow = (uint32_t)(wm * (BMt/2) + (lane & 15));
    uint32_t aColB = (lane >> 4) * 16;
    uint32_t aBaseOff = (aRow * LDK) * 4 + aColB;
    uint32_t bRow = (uint32_t)(wn * 64 + (lane & 7) + ((lane & 16) >> 1));
    uint32_t bColB = (lane & 8) * 2;
    uint32_t bBaseOff = (bRow * LDK) * 4 + bColB;

    int ntiles = K / BK;
    stage(0, 0);
    for (int i = 0; i < ntiles; i++) {
        if (i + 1 < ntiles) {
            stage((i + 1) & 1, (i + 1) * BK);
            asm volatile("cp.async.wait_group 1;\n" ::: "memory");
        } else {
            asm volatile("cp.async.wait_group 0;\n" ::: "memory");
        }
        __syncthreads();

        uint32_t sAb = (uint32_t)__cvta_generic_to_shared(As + (i & 1) * BMt * LDK);
        uint32_t sBb = (uint32_t)__cvta_generic_to_shared(Bs + (i & 1) * BN * LDK);
        uint32_t aAddr = sAb + aBaseOff;
        uint32_t bAddr = sBb + bBaseOff;

        #pragma unroll
        for (int kk = 0; kk < BK; kk += 8) {
            uint32_t af[MT][4];
            #pragma unroll
            for (int mt = 0; mt < MT; mt++)
                ldsm4(af[mt][0], af[mt][1], af[mt][2], af[mt][3],
                      aAddr + (uint32_t)(mt * 16 * LDK + kk) * 4);
            uint32_t bf[8][2];
            #pragma unroll
            for (int ntp = 0; ntp < 4; ntp++)
                ldsm4(bf[2*ntp][0], bf[2*ntp][1], bf[2*ntp+1][0], bf[2*ntp+1][1],
                      bAddr + (uint32_t)(ntp * 16 * LDK + kk) * 4);
            #pragma unroll
            for (int mt = 0; mt < MT; mt++)
                #pragma unroll
                for (int nt = 0; nt < 8; nt++) {
                    asm volatile(
                        "mma.sync.aligned.m16n8k8.row.col.f32.tf32.tf32.f32 "
                        "{%0,%1,%2,%3}, {%4,%5,%6,%7}, {%8,%9}, {%0,%1,%2,%3};"
                        : "+f"(acc[mt][nt][0]), "+f"(acc[mt][nt][1]),
                          "+f"(acc[mt][nt][2]), "+f"(acc[mt][nt][3])
                        : "r"(af[mt][0]), "r"(af[mt][1]), "r"(af[mt][2]), "r"(af[mt][3]),
                          "r"(bf[nt][0]), "r"(bf[nt][1]));
                }
        }
        __syncthreads();
    }

    int gg = lane >> 2, tt = lane & 3;
    #pragma unroll
    for (int mt = 0; mt < MT; mt++) {
        #pragma unroll
        for (int nt = 0; nt < 8; nt++) {
            int mbase = m0 + wm * (BMt/2) + mt * 16 + gg;
            int nn = n0 + wn * 64 + nt * 8 + 2 * tt;
            if (nn < N) {
                #pragma unroll
                for (int rhalf = 0; rhalf < 2; rhalf++) {
                    int mm = mbase + rhalf * 8;
                    float v0 = acc[mt][nt][rhalf*2 + 0];
                    float v1 = acc[mt][nt][rhalf*2 + 1];
                    if (EPI == 1) {
                        v0 += bias[nn];     v1 += bias[nn+1];
                        v0 = 0.5f * v0 * (1.f + erff(v0 * 0.70710678118654752f));
                        v1 = 0.5f * v1 * (1.f + erff(v1 * 0.70710678118654752f));
                        v0 = rnd_tf32(v0);  v1 = rnd_tf32(v1);
                    } else if (EPI == 2) {
                        float2 r = *(const float2*)&resid[(size_t)mm * N + nn];
                        v0 += r.x; v1 += r.y;
                    } else if (EPI == 3) {
                        float2 r = *(const float2*)&resid[(size_t)mm * N + nn];
                        v0 += bias[nn] + r.x; v1 += bias[nn+1] + r.y;
                    }
                    *(float2*)&C[(size_t)mm * N + nn] = make_float2(v0, v1);
                }
            }
        }
    }
}

// ---------------- chunked scan pass 1: fused conv(k=4)+silu + dt/dA + local scan ----------------
__global__ void scan1_kernel(const float* __restrict__ zx, const float* __restrict__ cw,
                             const float* __restrict__ cb,
                             const float* __restrict__ dtb, const float* __restrict__ Alog,
                             const float* __restrict__ D_ssm,
                             float* __restrict__ y, float* __restrict__ bcout,
                             float* __restrict__ hfin,
                             float* __restrict__ cuma, float* __restrict__ P) {
    int blk = blockIdx.x;
    int c = blk % NCHUNK;
    int bh = blk / NCHUNK;
    int h = bh % NHQ, b = bh / NHQ;
    int p = threadIdx.x;
    int lane = p & 31;

    int chx  = h * HDQ + p;
    int chbc = DIQ + lane;
    int colx  = DIQ + chx;
    int colbc = DIQ + chbc;

    float cwx[DCONVQ], cwb[DCONVQ];
    #pragma unroll
    for (int j = 0; j < DCONVQ; j++) {
        cwx[j] = cw[chx*DCONVQ + j];
        cwb[j] = cw[chbc*DCONVQ + j];
    }
    float cbx = cb[chx], cbb = cb[chbc];

    float Dh = D_ssm[h];
    float dtbh = dtb[h];
    float eA = expf(Alog[h]);

    int l0 = c * CLEN;
    size_t rowbase = (size_t)b * LQ;

    float xw0=0.f, xw1=0.f, xw2=0.f, bw0=0.f, bw1=0.f, bw2=0.f;
    {
        int ll = l0 - 3;
        if (ll >= 0) { size_t r = rowbase + ll; xw0 = zx[r*DPROJQ + colx]; bw0 = zx[r*DPROJQ + colbc]; }
        ll = l0 - 2;
        if (ll >= 0) { size_t r = rowbase + ll; xw1 = zx[r*DPROJQ + colx]; bw1 = zx[r*DPROJQ + colbc]; }
        ll = l0 - 1;
        if (ll >= 0) { size_t r = rowbase + ll; xw2 = zx[r*DPROJQ + colx]; bw2 = zx[r*DPROJQ + colbc]; }
    }

    float hs[NSQ];
    #pragma unroll
    for (int n = 0; n < NSQ; n++) hs[n] = 0.f;
    float cum = 1.f;

    for (int l = l0; l < l0 + CLEN; l++) {
        size_t row = rowbase + l;
        float xn = zx[row*DPROJQ + colx];
        float bn = zx[row*DPROJQ + colbc];
        float accx = cbx;
        accx = fmaf(xw0, cwx[0], accx);
        accx = fmaf(xw1, cwx[1], accx);
        accx = fmaf(xw2, cwx[2], accx);
        accx = fmaf(xn,  cwx[3], accx);
        float accb = cbb;
        accb = fmaf(bw0, cwb[0], accb);
        accb = fmaf(bw1, cwb[1], accb);
        accb = fmaf(bw2, cwb[2], accb);
        accb = fmaf(bn,  cwb[3], accb);
        xw0 = xw1; xw1 = xw2; xw2 = xn;
        bw0 = bw1; bw1 = bw2; bw2 = bn;

        float xv  = accx / (1.f + expf(-accx));
        float bcv = accb / (1.f + expf(-accb));
        if (h == 0 && p < 32) bcout[row*(2*NSQ) + lane] = bcv;

        float raw = zx[row*DPROJQ + (DPROJQ - NHQ) + h] + dtbh;
        float dtv = (raw > 20.f) ? raw : log1pf(expf(raw));
        float a   = expf(-eA * dtv);
        cum *= a;
        if (p == 0) cuma[row*NHQ + h] = cum;

        float coef = dtv * xv;
        float acc = 0.f;
        #pragma unroll
        for (int n = 0; n < NSQ; n++) {
            float Bn = __shfl_sync(0xFFFFFFFFu, bcv, n);
            float Cn = __shfl_sync(0xFFFFFFFFu, bcv, 16 + n);
            hs[n] = fmaf(hs[n], a, coef * Bn);
            acc = fmaf(hs[n], Cn, acc);
        }
        y[row*DIQ + h*HDQ + p] = acc + Dh * xv;
    }
    size_t base = ((size_t)blk * HDQ + p) * NSQ;
    #pragma unroll
    for (int n = 0; n < NSQ; n++) hfin[base + n] = hs[n];
    if (p == 0) P[blk] = cum;
}

// ---------------- chunked scan pass 2 (4 blocks per bh) ----------------
__global__ void scan2_kernel(const float* __restrict__ hfin, const float* __restrict__ P,
                             float* __restrict__ hinit) {
    int bh = blockIdx.x >> 2;
    int e  = (blockIdx.x & 3) * 256 + threadIdx.x;
    float cur = 0.f;
    #pragma unroll 4
    for (int cc = 0; cc < NCHUNK; cc++) {
        size_t idx = (size_t)(bh * NCHUNK + cc) * (HDQ*NSQ) + e;
        hinit[idx] = cur;
        cur = P[bh * NCHUNK + cc] * cur + hfin[idx];
    }
}

// ---------------- chunked scan pass 3 (reads compact BC buffer) ----------------
__global__ void scan3_kernel(const float* __restrict__ bc, const float* __restrict__ cuma,
                             const float* __restrict__ hinit, float* __restrict__ y) {
    int blk = blockIdx.x;
    int c = blk % NCHUNK;
    if (c == 0) return;
    int bh = blk / NCHUNK;
    int h = bh % NHQ, b = bh / NHQ;
    int p = threadIdx.x;
    int lane = p & 31;
    float hi[NSQ];
    size_t base = ((size_t)blk * HDQ + p) * NSQ;
    #pragma unroll
    for (int n = 0; n < NSQ; n++) hi[n] = hinit[base + n];
    int l0 = c * CLEN;
    for (int l = l0; l < l0 + CLEN; l++) {
        size_t row = (size_t)b * LQ + l;
        float bcv = bc[row*(2*NSQ) + lane];
        float ca  = cuma[row*NHQ + h];
        float corr = 0.f;
        #pragma unroll
        for (int n = 0; n < NSQ; n++)
            corr = fmaf(hi[n], __shfl_sync(0xFFFFFFFFu, bcv, 16 + n), corr);
        y[row*DIQ + h*HDQ + p] += ca * corr;
    }
}

// ---------------- gated RMSNorm over DI=1024 ----------------
__global__ void gate_norm_kernel(float* __restrict__ y, const float* __restrict__ zx,
                                 const float* __restrict__ gw) {
    __shared__ float sh[32];
    int m = blockIdx.x;
    int t = threadIdx.x;
    float v[4]; float ss = 0.f;
    #pragma unroll
    for (int i = 0; i < 4; i++) {
        int c = t + i*256;
        float z = zx[(size_t)m*DPROJQ + c];
        float yy = y[(size_t)m*DIQ + c];
        float g = z / (1.f + expf(-z));
        v[i] = yy * g;
        ss += v[i]*v[i];
    }
    float tot = block_reduce_sum(ss, sh);
    float scale = rsqrtf(tot * (1.f/DIQ) + EPSQ);
    #pragma unroll
    for (int i = 0; i < 4; i++) {
        int c = t + i*256;
        y[(size_t)m*DIQ + c] = rnd_tf32(v[i] * scale * gw[c]);
    }
}

// ---------------- launcher ----------------
extern "C" void kernel_launch(void* const* d_in, const int* in_sizes, int n_in,
                              void* d_out, int out_size) {
    const float* x          = (const float*)d_in[0];
    const float* in_proj_w  = (const float*)d_in[1];
    const float* conv_w     = (const float*)d_in[2];
    const float* conv_b     = (const float*)d_in[3];
    const float* dt_bias    = (const float*)d_in[4];
    const float* A_log      = (const float*)d_in[5];
    const float* D_ssm      = (const float*)d_in[6];
    const float* gnorm_w    = (const float*)d_in[7];
    const float* out_proj_w = (const float*)d_in[8];
    const float* ffn_w1     = (const float*)d_in[9];
    const float* ffn_b1     = (const float*)d_in[10];
    const float* ffn_w2     = (const float*)d_in[11];
    const float* ffn_b2     = (const float*)d_in[12];
    const float* norm_mamba = (const float*)d_in[13];
    const float* norm_ffn   = (const float*)d_in[14];
    const float* final_norm = (const float*)d_in[15];
    float* out = (float*)d_out;

    float *gx, *gxn, *gzx, *gbc, *gy, *gh1;
    float *ghfin, *ghinit, *gcuma, *gP, *gwip, *gwop, *gw1, *gw2;
    cudaGetSymbolAddress((void**)&gx,  g_x);
    cudaGetSymbolAddress((void**)&gxn, g_xn);
    cudaGetSymbolAddress((void**)&gzx, g_zx);
    cudaGetSymbolAddress((void**)&gbc, g_bc);
    cudaGetSymbolAddress((void**)&gy,  g_y);
    cudaGetSymbolAddress((void**)&gh1, g_h1);
    cudaGetSymbolAddress((void**)&ghfin, g_hfin);
    cudaGetSymbolAddress((void**)&ghinit,g_hinit);
    cudaGetSymbolAddress((void**)&gcuma, g_cuma);
    cudaGetSymbolAddress((void**)&gP,    g_P);
    cudaGetSymbolAddress((void**)&gwip,  g_wip);
    cudaGetSymbolAddress((void**)&gwop,  g_wop);
    cudaGetSymbolAddress((void**)&gw1,   g_w1);
    cudaGetSymbolAddress((void**)&gw2,   g_w2);

    const int smem128 = (2*128*LDK + 2*BN*LDK) * 4;
    const int smem64  = (2*64 *LDK + 2*BN*LDK) * 4;
    cudaFuncSetAttribute(gemm_tc4<0,128>, cudaFuncAttributeMaxDynamicSharedMemorySize, smem128);
    cudaFuncSetAttribute(gemm_tc4<1,128>, cudaFuncAttributeMaxDynamicSharedMemorySize, smem128);
    cudaFuncSetAttribute(gemm_tc4<2,64>,  cudaFuncAttributeMaxDynamicSharedMemorySize, smem64);
    cudaFuncSetAttribute(gemm_tc4<3,64>,  cudaFuncAttributeMaxDynamicSharedMemorySize, smem64);

    // pre-round all weights to tf32 bit patterns (one fused launch)
    cvt4_tf32_kernel<<<2048, 256>>>(
        in_proj_w,  gwip, NLAYERSQ*DPROJQ*DMQ,
        out_proj_w, gwop, NLAYERSQ*DMQ*DIQ,
        ffn_w1,     gw1,  NLAYERSQ*DFFQ*DMQ,
        ffn_w2,     gw2,  NLAYERSQ*DMQ*DFFQ);

    for (int i = 0; i < NLAYERSQ; i++) {
        // --- mamba block ---
        if (i == 0) {
            rmsnorm_kernel<1><<<BLQ, 128>>>(x, norm_mamba, gxn, gx, 1);
        } else {
            rmsnorm_kernel<0><<<BLQ, 128>>>(gx, norm_mamba + i*DMQ, gxn, nullptr, 1);
        }

        gemm_tc4<0,128><<<dim3((DPROJQ+BN-1)/BN, BLQ/128), 128, smem128>>>(
            gxn, gwip + (size_t)i*DPROJQ*DMQ, gzx, nullptr, nullptr,
            BLQ, DPROJQ, DMQ);

        scan1_kernel<<<BQ*NHQ*NCHUNK, HDQ>>>(
            gzx, conv_w + (size_t)i*CONV_DIMQ*DCONVQ, conv_b + (size_t)i*CONV_DIMQ,
            dt_bias + i*NHQ, A_log + i*NHQ, D_ssm + i*NHQ,
            gy, gbc, ghfin, gcuma, gP);
        scan2_kernel<<<BQ*NHQ*4, 256>>>(ghfin, gP, ghinit);
        scan3_kernel<<<BQ*NHQ*NCHUNK, HDQ>>>(gbc, gcuma, ghinit, gy);

        gate_norm_kernel<<<BLQ, 256>>>(gy, gzx, gnorm_w + (size_t)i*DIQ);

        gemm_tc4<2,64><<<dim3(DMQ/BN, BLQ/64), 128, smem64>>>(
            gy, gwop + (size_t)i*DMQ*DIQ, gx, nullptr, gx,
            BLQ, DMQ, DIQ);

        // --- ffn block ---
        rmsnorm_kernel<0><<<BLQ, 128>>>(gx, norm_ffn + i*DMQ, gxn, nullptr, 1);

        gemm_tc4<1,128><<<dim3(DFFQ/BN, BLQ/128), 128, smem128>>>(
            gxn, gw1 + (size_t)i*DFFQ*DMQ, gh1, ffn_b1 + (size_t)i*DFFQ, nullptr,
            BLQ, DFFQ, DMQ);

        gemm_tc4<3,64><<<dim3(DMQ/BN, BLQ/64), 128, smem64>>>(
            gh1, gw2 + (size_t)i*DMQ*DFFQ, gx, ffn_b2 + (size_t)i*DMQ, gx,
            BLQ, DMQ, DFFQ);
    }

    rmsnorm_kernel<0><<<BLQ, 128>>>(gx, final_norm, out, nullptr, 0);
}

// round 12
// speedup vs baseline: 1.0740x; 1.0087x over previous
#include <cuda_runtime.h>
#include <math.h>
#include <stdint.h>

// ---------------- problem constants ----------------
#define BQ 4
#define LQ 1024
#define DMQ 512
#define DIQ 1024
#define NHQ 16
#define HDQ 64
#define NSQ 16
#define DCONVQ 4
#define CONV_DIMQ 1056
#define DPROJQ 2096
#define DFFQ 2048
#define NLAYERSQ 6
#define BLQ (BQ*LQ)          // 4096 rows
#define EPSQ 1e-5f

// GEMM tiling
#define BN 128
#define BK 32
#define LDK 36               // padded k-stride (floats); 144B = 9*16B -> ldmatrix-aligned, conflict-free

// scan chunking
#define NCHUNK 64
#define CLEN (LQ/NCHUNK)     // 16

// ---------------- scratch (device globals, no allocation) ----------------
__device__ float g_x  [BLQ*DMQ];
__device__ float g_xn [BLQ*DMQ];
__device__ float g_zx [BLQ*DPROJQ];
__device__ float g_bc [BLQ*2*NSQ];       // conv+silu'd B,C (compact)
__device__ float g_dt [BLQ*NHQ];
__device__ float g_dA [BLQ*NHQ];
__device__ float g_y  [BLQ*DIQ];
__device__ float g_h1 [BLQ*DFFQ];
__device__ float g_hfin [BQ*NHQ*NCHUNK*HDQ*NSQ];
__device__ float g_hinit[BQ*NHQ*NCHUNK*HDQ*NSQ];
__device__ float g_cuma [BLQ*NHQ];
__device__ float g_P    [BQ*NHQ*NCHUNK];
__device__ float g_wip[NLAYERSQ*DPROJQ*DMQ];
__device__ float g_wop[NLAYERSQ*DMQ*DIQ];
__device__ float g_w1 [NLAYERSQ*DFFQ*DMQ];
__device__ float g_w2 [NLAYERSQ*DMQ*DFFQ];

// ---------------- helpers ----------------
__device__ __forceinline__ float block_reduce_sum(float v, float* sh) {
    int lane = threadIdx.x & 31, wid = threadIdx.x >> 5;
    #pragma unroll
    for (int o = 16; o; o >>= 1) v += __shfl_xor_sync(0xFFFFFFFFu, v, o);
    if (lane == 0) sh[wid] = v;
    __syncthreads();
    int nw = blockDim.x >> 5;
    v = (threadIdx.x < nw) ? sh[threadIdx.x] : 0.f;
    if (wid == 0) {
        #pragma unroll
        for (int o = 16; o; o >>= 1) v += __shfl_xor_sync(0xFFFFFFFFu, v, o);
        if (lane == 0) sh[0] = v;
    }
    __syncthreads();
    float r = sh[0];
    __syncthreads();
    return r;
}

__device__ __forceinline__ uint32_t f2tf32(float f) {
    uint32_t u;
    asm("cvt.rna.tf32.f32 %0, %1;" : "=r"(u) : "f"(f));
    return u;
}
__device__ __forceinline__ float rnd_tf32(float f) { return __uint_as_float(f2tf32(f)); }

__device__ __forceinline__ void cp16(uint32_t dst, const void* src, bool pred) {
    int sz = pred ? 16 : 0;
    asm volatile("cp.async.cg.shared.global [%0], [%1], 16, %2;\n"
                 :: "r"(dst), "l"(src), "r"(sz) : "memory");
}
__device__ __forceinline__ void cp_commit() {
    asm volatile("cp.async.commit_group;\n" ::: "memory");
}

__device__ __forceinline__ void ldsm4(uint32_t& r0, uint32_t& r1, uint32_t& r2, uint32_t& r3,
                                      uint32_t addr) {
    asm volatile("ldmatrix.sync.aligned.m8n8.x4.shared.b16 {%0,%1,%2,%3}, [%4];"
                 : "=r"(r0), "=r"(r1), "=r"(r2), "=r"(r3) : "r"(addr));
}

// fused 4-tensor tf32 rounding (grid-stride per segment)
__global__ void cvt4_tf32_kernel(const float* __restrict__ i0, float* __restrict__ o0, int n0,
                                 const float* __restrict__ i1, float* __restrict__ o1, int n1,
                                 const float* __restrict__ i2, float* __restrict__ o2, int n2,
                                 const float* __restrict__ i3, float* __restrict__ o3, int n3) {
    int stride4 = gridDim.x * blockDim.x * 4;
    int base = (blockIdx.x * blockDim.x + threadIdx.x) * 4;
    #pragma unroll
    for (int seg = 0; seg < 4; seg++) {
        const float* in  = (seg==0) ? i0 : (seg==1) ? i1 : (seg==2) ? i2 : i3;
        float* out       = (seg==0) ? o0 : (seg==1) ? o1 : (seg==2) ? o2 : o3;
        int n            = (seg==0) ? n0 : (seg==1) ? n1 : (seg==2) ? n2 : n3;
        for (int i = base; i < n; i += stride4) {
            float4 v = *(const float4*)&in[i];
            v.x = rnd_tf32(v.x); v.y = rnd_tf32(v.y);
            v.z = rnd_tf32(v.z); v.w = rnd_tf32(v.w);
            *(float4*)&out[i] = v;
        }
    }
}

// ---------------- rmsnorm over DM=512 ----------------
template<int COPY>
__global__ void rmsnorm_kernel(const float* __restrict__ in, const float* __restrict__ w,
                               float* __restrict__ out, float* __restrict__ xcopy,
                               int round_out) {
    __shared__ float sh[32];
    int m = blockIdx.x;
    int t = threadIdx.x;
    const float* row = in + (size_t)m * DMQ;
    float v[4]; float ss = 0.f;
    #pragma unroll
    for (int i = 0; i < 4; i++) { v[i] = row[t + i*128]; ss += v[i]*v[i]; }
    float tot = block_reduce_sum(ss, sh);
    float scale = rsqrtf(tot * (1.f/DMQ) + EPSQ);
    float* orow = out + (size_t)m * DMQ;
    #pragma unroll
    for (int i = 0; i < 4; i++) {
        float o = v[i] * scale * w[t + i*128];
        orow[t + i*128] = round_out ? rnd_tf32(o) : o;
        if (COPY) xcopy[(size_t)m * DMQ + t + i*128] = v[i];
    }
}

// ---------------- tensor-core GEMM (R5 best config) ----------------
template<int EPI, int BMt>
__global__ void __launch_bounds__(128, (BMt==128) ? 2 : 3)
gemm_tc4(const float* __restrict__ A, const float* __restrict__ W,
         float* __restrict__ C, const float* __restrict__ bias,
         const float* __restrict__ resid, int M, int N, int K) {
    constexpr int MT = BMt / 32;
    extern __shared__ float sm[];
    float* As = sm;                        // [2][BMt][LDK]
    float* Bs = sm + 2 * BMt * LDK;        // [2][BN][LDK]

    int tid  = threadIdx.x;
    int warp = tid >> 5, lane = tid & 31;
    int wm = warp & 1;
    int wn = warp >> 1;

    int m0 = blockIdx.y * BMt;
    int n0 = blockIdx.x * BN;

    float acc[MT][8][4];
    #pragma unroll
    for (int i = 0; i < MT; i++)
        #pragma unroll
        for (int j = 0; j < 8; j++)
            #pragma unroll
            for (int c = 0; c < 4; c++) acc[i][j][c] = 0.f;

    auto stage = [&](int buf, int k0) {
        float* Ab = As + buf * BMt * LDK;
        #pragma unroll
        for (int it = 0; it < (BMt*8)/128; it++) {
            int ch = it * 128 + tid;
            int r = ch >> 3, kc = (ch & 7) * 4;
            uint32_t dst = (uint32_t)__cvta_generic_to_shared(&Ab[r * LDK + kc]);
            cp16(dst, &A[(size_t)(m0 + r) * K + k0 + kc], true);
        }
        float* Bb = Bs + buf * BN * LDK;
        #pragma unroll
        for (int it = 0; it < 8; it++) {
            int ch = it * 128 + tid;
            int r = ch >> 3, kc = (ch & 7) * 4;
            int n = n0 + r;
            bool ok = (n < N);
            uint32_t dst = (uint32_t)__cvta_generic_to_shared(&Bb[r * LDK + kc]);
            cp16(dst, &W[(size_t)(ok ? n : 0) * K + k0 + kc], ok);
        }
        cp_commit();
    };

    uint32_t aRow = (uint32_t)(wm * (BMt/2) + (lane & 15));
    uint32_t aColB = (lane >> 4) * 16;
    uint32_t aBaseOff = (aRow * LDK) * 4 + aColB;
    uint32_t bRow = (uint32_t)(wn * 64 + (lane & 7) + ((lane & 16) >> 1));
    uint32_t bColB = (lane & 8) * 2;
    uint32_t bBaseOff = (bRow * LDK) * 4 + bColB;

    int ntiles = K / BK;
    stage(0, 0);
    for (int i = 0; i < ntiles; i++) {
        if (i + 1 < ntiles) {
            stage((i + 1) & 1, (i + 1) * BK);
            asm volatile("cp.async.wait_group 1;\n" ::: "memory");
        } else {
            asm volatile("cp.async.wait_group 0;\n" ::: "memory");
        }
        __syncthreads();

        uint32_t sAb = (uint32_t)__cvta_generic_to_shared(As + (i & 1) * BMt * LDK);
        uint32_t sBb = (uint32_t)__cvta_generic_to_shared(Bs + (i & 1) * BN * LDK);
        uint32_t aAddr = sAb + aBaseOff;
        uint32_t bAddr = sBb + bBaseOff;

        #pragma unroll
        for (int kk = 0; kk < BK; kk += 8) {
            uint32_t af[MT][4];
            #pragma unroll
            for (int mt = 0; mt < MT; mt++)
                ldsm4(af[mt][0], af[mt][1], af[mt][2], af[mt][3],
                      aAddr + (uint32_t)(mt * 16 * LDK + kk) * 4);
            uint32_t bf[8][2];
            #pragma unroll
            for (int ntp = 0; ntp < 4; ntp++)
                ldsm4(bf[2*ntp][0], bf[2*ntp][1], bf[2*ntp+1][0], bf[2*ntp+1][1],
                      bAddr + (uint32_t)(ntp * 16 * LDK + kk) * 4);
            #pragma unroll
            for (int mt = 0; mt < MT; mt++)
                #pragma unroll
                for (int nt = 0; nt < 8; nt++) {
                    asm volatile(
                        "mma.sync.aligned.m16n8k8.row.col.f32.tf32.tf32.f32 "
                        "{%0,%1,%2,%3}, {%4,%5,%6,%7}, {%8,%9}, {%0,%1,%2,%3};"
                        : "+f"(acc[mt][nt][0]), "+f"(acc[mt][nt][1]),
                          "+f"(acc[mt][nt][2]), "+f"(acc[mt][nt][3])
                        : "r"(af[mt][0]), "r"(af[mt][1]), "r"(af[mt][2]), "r"(af[mt][3]),
                          "r"(bf[nt][0]), "r"(bf[nt][1]));
                }
        }
        __syncthreads();
    }

    int gg = lane >> 2, tt = lane & 3;
    #pragma unroll
    for (int mt = 0; mt < MT; mt++) {
        #pragma unroll
        for (int nt = 0; nt < 8; nt++) {
            int mbase = m0 + wm * (BMt/2) + mt * 16 + gg;
            int nn = n0 + wn * 64 + nt * 8 + 2 * tt;
            if (nn < N) {
                #pragma unroll
                for (int rhalf = 0; rhalf < 2; rhalf++) {
                    int mm = mbase + rhalf * 8;
                    float v0 = acc[mt][nt][rhalf*2 + 0];
                    float v1 = acc[mt][nt][rhalf*2 + 1];
                    if (EPI == 1) {
                        v0 += bias[nn];     v1 += bias[nn+1];
                        v0 = 0.5f * v0 * (1.f + erff(v0 * 0.70710678118654752f));
                        v1 = 0.5f * v1 * (1.f + erff(v1 * 0.70710678118654752f));
                        v0 = rnd_tf32(v0);  v1 = rnd_tf32(v1);
                    } else if (EPI == 2) {
                        float2 r = *(const float2*)&resid[(size_t)mm * N + nn];
                        v0 += r.x; v1 += r.y;
                    } else if (EPI == 3) {
                        float2 r = *(const float2*)&resid[(size_t)mm * N + nn];
                        v0 += bias[nn] + r.x; v1 += bias[nn+1] + r.y;
                    }
                    *(float2*)&C[(size_t)mm * N + nn] = make_float2(v0, v1);
                }
            }
        }
    }
}

// ---------------- prep: bc conv+silu, dt (softplus), dA (exp) ----------------
// one thread per output; BLQ*48 outputs (j<32: bc channel, j>=32: head dt/dA)
__global__ void prep_kernel(const float* __restrict__ zx, const float* __restrict__ cw,
                            const float* __restrict__ cb,
                            const float* __restrict__ dtb, const float* __restrict__ Alog,
                            float* __restrict__ bc, float* __restrict__ dt,
                            float* __restrict__ dA) {
    int idx = blockIdx.x * blockDim.x + threadIdx.x;
    if (idx >= BLQ * 48) return;
    int row = idx / 48;
    int j = idx % 48;
    int b = row / LQ, l = row % LQ;
    if (j < 2*NSQ) {
        int ch = DIQ + j;                 // conv channel
        int col = DIQ + ch;               // zx column
        float acc = cb[ch];
        #pragma unroll
        for (int t = 0; t < DCONVQ; t++) {
            int ll = l - (DCONVQ-1) + t;
            if (ll >= 0)
                acc = fmaf(zx[(size_t)(b*LQ + ll)*DPROJQ + col], cw[ch*DCONVQ + t], acc);
        }
        bc[(size_t)row*(2*NSQ) + j] = acc / (1.f + expf(-acc));
    } else {
        int h = j - 2*NSQ;
        float raw = zx[(size_t)row*DPROJQ + (DPROJQ - NHQ) + h] + dtb[h];
        float dtv = (raw > 20.f) ? raw : log1pf(expf(raw));
        dt[(size_t)row*NHQ + h] = dtv;
        dA[(size_t)row*NHQ + h] = expf(-expf(Alog[h]) * dtv);
    }
}

// ---------------- chunked scan pass 1: x-conv + local scan (bc/dt/dA preloaded) ----------------
__global__ void scan1_kernel(const float* __restrict__ zx, const float* __restrict__ cw,
                             const float* __restrict__ cb,
                             const float* __restrict__ bcin, const float* __restrict__ dt,
                             const float* __restrict__ dA, const float* __restrict__ D_ssm,
                             float* __restrict__ y, float* __restrict__ hfin,
                             float* __restrict__ cuma, float* __restrict__ P) {
    int blk = blockIdx.x;
    int c = blk % NCHUNK;
    int bh = blk / NCHUNK;
    int h = bh % NHQ, b = bh / NHQ;
    int p = threadIdx.x;
    int lane = p & 31;

    int chx = h * HDQ + p;
    int colx = DIQ + chx;

    float cwx[DCONVQ];
    #pragma unroll
    for (int j = 0; j < DCONVQ; j++) cwx[j] = cw[chx*DCONVQ + j];
    float cbx = cb[chx];
    float Dh = D_ssm[h];

    int l0 = c * CLEN;
    size_t rowbase = (size_t)b * LQ;

    float xw0=0.f, xw1=0.f, xw2=0.f;
    {
        int ll = l0 - 3;
        if (ll >= 0) xw0 = zx[(rowbase + ll)*DPROJQ + colx];
        ll = l0 - 2;
        if (ll >= 0) xw1 = zx[(rowbase + ll)*DPROJQ + colx];
        ll = l0 - 1;
        if (ll >= 0) xw2 = zx[(rowbase + ll)*DPROJQ + colx];
    }

    float hs[NSQ];
    #pragma unroll
    for (int n = 0; n < NSQ; n++) hs[n] = 0.f;
    float cum = 1.f;

    for (int l = l0; l < l0 + CLEN; l++) {
        size_t row = rowbase + l;
        float xn = zx[row*DPROJQ + colx];
        float accx = cbx;
        accx = fmaf(xw0, cwx[0], accx);
        accx = fmaf(xw1, cwx[1], accx);
        accx = fmaf(xw2, cwx[2], accx);
        accx = fmaf(xn,  cwx[3], accx);
        xw0 = xw1; xw1 = xw2; xw2 = xn;

        float xv  = accx / (1.f + expf(-accx));
        float bcv = bcin[row*(2*NSQ) + lane];
        float dtv = dt[row*NHQ + h];
        float a   = dA[row*NHQ + h];
        cum *= a;
        if (p == 0) cuma[row*NHQ + h] = cum;

        float coef = dtv * xv;
        float acc = 0.f;
        #pragma unroll
        for (int n = 0; n < NSQ; n++) {
            float Bn = __shfl_sync(0xFFFFFFFFu, bcv, n);
            float Cn = __shfl_sync(0xFFFFFFFFu, bcv, 16 + n);
            hs[n] = fmaf(hs[n], a, coef * Bn);
            acc = fmaf(hs[n], Cn, acc);
        }
        y[row*DIQ + h*HDQ + p] = acc + Dh * xv;
    }
    size_t base = ((size_t)blk * HDQ + p) * NSQ;
    #pragma unroll
    for (int n = 0; n < NSQ; n++) hfin[base + n] = hs[n];
    if (p == 0) P[blk] = cum;
}

// ---------------- chunked scan pass 2 (4 blocks per bh) ----------------
__global__ void scan2_kernel(const float* __restrict__ hfin, const float* __restrict__ P,
                             float* __restrict__ hinit) {
    int bh = blockIdx.x >> 2;
    int e  = (blockIdx.x & 3) * 256 + threadIdx.x;
    float cur = 0.f;
    #pragma unroll 4
    for (int cc = 0; cc < NCHUNK; cc++) {
        size_t idx = (size_t)(bh * NCHUNK + cc) * (HDQ*NSQ) + e;
        hinit[idx] = cur;
        cur = P[bh * NCHUNK + cc] * cur + hfin[idx];
    }
}

// ---------------- chunked scan pass 3 (reads compact BC buffer) ----------------
__global__ void scan3_kernel(const float* __restrict__ bc, const float* __restrict__ cuma,
                             const float* __restrict__ hinit, float* __restrict__ y) {
    int blk = blockIdx.x;
    int c = blk % NCHUNK;
    if (c == 0) return;
    int bh = blk / NCHUNK;
    int h = bh % NHQ, b = bh / NHQ;
    int p = threadIdx.x;
    int lane = p & 31;
    float hi[NSQ];
    size_t base = ((size_t)blk * HDQ + p) * NSQ;
    #pragma unroll
    for (int n = 0; n < NSQ; n++) hi[n] = hinit[base + n];
    int l0 = c * CLEN;
    for (int l = l0; l < l0 + CLEN; l++) {
        size_t row = (size_t)b * LQ + l;
        float bcv = bc[row*(2*NSQ) + lane];
        float ca  = cuma[row*NHQ + h];
        float corr = 0.f;
        #pragma unroll
        for (int n = 0; n < NSQ; n++)
            corr = fmaf(hi[n], __shfl_sync(0xFFFFFFFFu, bcv, 16 + n), corr);
        y[row*DIQ + h*HDQ + p] += ca * corr;
    }
}

// ---------------- gated RMSNorm over DI=1024 ----------------
__global__ void gate_norm_kernel(float* __restrict__ y, const float* __restrict__ zx,
                                 const float* __restrict__ gw) {
    __shared__ float sh[32];
    int m = blockIdx.x;
    int t = threadIdx.x;
    float v[4]; float ss = 0.f;
    #pragma unroll
    for (int i = 0; i < 4; i++) {
        int c = t + i*256;
        float z = zx[(size_t)m*DPROJQ + c];
        float yy = y[(size_t)m*DIQ + c];
        float g = z / (1.f + expf(-z));
        v[i] = yy * g;
        ss += v[i]*v[i];
    }
    float tot = block_reduce_sum(ss, sh);
    float scale = rsqrtf(tot * (1.f/DIQ) + EPSQ);
    #pragma unroll
    for (int i = 0; i < 4; i++) {
        int c = t + i*256;
        y[(size_t)m*DIQ + c] = rnd_tf32(v[i] * scale * gw[c]);
    }
}

// ---------------- launcher ----------------
extern "C" void kernel_launch(void* const* d_in, const int* in_sizes, int n_in,
                              void* d_out, int out_size) {
    const float* x          = (const float*)d_in[0];
    const float* in_proj_w  = (const float*)d_in[1];
    const float* conv_w     = (const float*)d_in[2];
    const float* conv_b     = (const float*)d_in[3];
    const float* dt_bias    = (const float*)d_in[4];
    const float* A_log      = (const float*)d_in[5];
    const float* D_ssm      = (const float*)d_in[6];
    const float* gnorm_w    = (const float*)d_in[7];
    const float* out_proj_w = (const float*)d_in[8];
    const float* ffn_w1     = (const float*)d_in[9];
    const float* ffn_b1     = (const float*)d_in[10];
    const float* ffn_w2     = (const float*)d_in[11];
    const float* ffn_b2     = (const float*)d_in[12];
    const float* norm_mamba = (const float*)d_in[13];
    const float* norm_ffn   = (const float*)d_in[14];
    const float* final_norm = (const float*)d_in[15];
    float* out = (float*)d_out;

    float *gx, *gxn, *gzx, *gbc, *gdt, *gdA, *gy, *gh1;
    float *ghfin, *ghinit, *gcuma, *gP, *gwip, *gwop, *gw1, *gw2;
    cudaGetSymbolAddress((void**)&gx,  g_x);
    cudaGetSymbolAddress((void**)&gxn, g_xn);
    cudaGetSymbolAddress((void**)&gzx, g_zx);
    cudaGetSymbolAddress((void**)&gbc, g_bc);
    cudaGetSymbolAddress((void**)&gdt, g_dt);
    cudaGetSymbolAddress((void**)&gdA, g_dA);
    cudaGetSymbolAddress((void**)&gy,  g_y);
    cudaGetSymbolAddress((void**)&gh1, g_h1);
    cudaGetSymbolAddress((void**)&ghfin, g_hfin);
    cudaGetSymbolAddress((void**)&ghinit,g_hinit);
    cudaGetSymbolAddress((void**)&gcuma, g_cuma);
    cudaGetSymbolAddress((void**)&gP,    g_P);
    cudaGetSymbolAddress((void**)&gwip,  g_wip);
    cudaGetSymbolAddress((void**)&gwop,  g_wop);
    cudaGetSymbolAddress((void**)&gw1,   g_w1);
    cudaGetSymbolAddress((void**)&gw2,   g_w2);

    const int smem128 = (2*128*LDK + 2*BN*LDK) * 4;
    const int smem64  = (2*64 *LDK + 2*BN*LDK) * 4;
    cudaFuncSetAttribute(gemm_tc4<0,128>, cudaFuncAttributeMaxDynamicSharedMemorySize, smem128);
    cudaFuncSetAttribute(gemm_tc4<1,128>, cudaFuncAttributeMaxDynamicSharedMemorySize, smem128);
    cudaFuncSetAttribute(gemm_tc4<2,64>,  cudaFuncAttributeMaxDynamicSharedMemorySize, smem64);
    cudaFuncSetAttribute(gemm_tc4<3,64>,  cudaFuncAttributeMaxDynamicSharedMemorySize, smem64);

    // pre-round all weights to tf32 bit patterns (one fused launch)
    cvt4_tf32_kernel<<<2048, 256>>>(
        in_proj_w,  gwip, NLAYERSQ*DPROJQ*DMQ,
        out_proj_w, gwop, NLAYERSQ*DMQ*DIQ,
        ffn_w1,     gw1,  NLAYERSQ*DFFQ*DMQ,
        ffn_w2,     gw2,  NLAYERSQ*DMQ*DFFQ);

    for (int i = 0; i < NLAYERSQ; i++) {
        // --- mamba block ---
        if (i == 0) {
            rmsnorm_kernel<1><<<BLQ, 128>>>(x, norm_mamba, gxn, gx, 1);
        } else {
            rmsnorm_kernel<0><<<BLQ, 128>>>(gx, norm_mamba + i*DMQ, gxn, nullptr, 1);
        }

        gemm_tc4<0,128><<<dim3((DPROJQ+BN-1)/BN, BLQ/128), 128, smem128>>>(
            gxn, gwip + (size_t)i*DPROJQ*DMQ, gzx, nullptr, nullptr,
            BLQ, DPROJQ, DMQ);

        prep_kernel<<<(BLQ*48 + 255)/256, 256>>>(
            gzx, conv_w + (size_t)i*CONV_DIMQ*DCONVQ, conv_b + (size_t)i*CONV_DIMQ,
            dt_bias + i*NHQ, A_log + i*NHQ, gbc, gdt, gdA);

        scan1_kernel<<<BQ*NHQ*NCHUNK, HDQ>>>(
            gzx, conv_w + (size_t)i*CONV_DIMQ*DCONVQ, conv_b + (size_t)i*CONV_DIMQ,
            gbc, gdt, gdA, D_ssm + i*NHQ,
            gy, ghfin, gcuma, gP);
        scan2_kernel<<<BQ*NHQ*4, 256>>>(ghfin, gP, ghinit);
        scan3_kernel<<<BQ*NHQ*NCHUNK, HDQ>>>(gbc, gcuma, ghinit, gy);

        gate_norm_kernel<<<BLQ, 256>>>(gy, gzx, gnorm_w + (size_t)i*DIQ);

        gemm_tc4<2,64><<<dim3(DMQ/BN, BLQ/64), 128, smem64>>>(
            gy, gwop + (size_t)i*DMQ*DIQ, gx, nullptr, gx,
            BLQ, DMQ, DIQ);

        // --- ffn block ---
        rmsnorm_kernel<0><<<BLQ, 128>>>(gx, norm_ffn + i*DMQ, gxn, nullptr, 1);

        gemm_tc4<1,128><<<dim3(DFFQ/BN, BLQ/128), 128, smem128>>>(
            gxn, gw1 + (size_t)i*DFFQ*DMQ, gh1, ffn_b1 + (size_t)i*DFFQ, nullptr,
            BLQ, DFFQ, DMQ);

        gemm_tc4<3,64><<<dim3(DMQ/BN, BLQ/64), 128, smem64>>>(
            gh1, gw2 + (size_t)i*DMQ*DFFQ, gx, ffn_b2 + (size_t)i*DMQ, gx,
            BLQ, DMQ, DFFQ);
    }

    rmsnorm_kernel<0><<<BLQ, 128>>>(gx, final_norm, out, nullptr, 0);
}

// round 15
// speedup vs baseline: 1.5385x; 1.4324x over previous
#include <cuda_runtime.h>
#include <cuda_fp16.h>
#include <math.h>
#include <stdint.h>

// ---------------- problem constants ----------------
#define BQ 4
#define LQ 1024
#define DMQ 512
#define DIQ 1024
#define NHQ 16
#define HDQ 64
#define NSQ 16
#define DCONVQ 4
#define CONV_DIMQ 1056
#define DPROJQ 2096
#define DFFQ 2048
#define NLAYERSQ 6
#define BLQ (BQ*LQ)          // 4096 rows
#define EPSQ 1e-5f

// GEMM tiling (fp16): BK=64 halves per tile (128B/row), LDKH=72 (144B stride, conflict-free)
#define BN 128
#define BK 64
#define LDKH 72

// scan chunking
#define NCHUNK 64
#define CLEN (LQ/NCHUNK)     // 16

// ---------------- scratch (device globals, no allocation) ----------------
__device__ float  g_x  [BLQ*DMQ];
__device__ __half g_xn [BLQ*DMQ];
__device__ float  g_zx [BLQ*DPROJQ];
__device__ float  g_bc [BLQ*2*NSQ];
__device__ float  g_dt [BLQ*NHQ];
__device__ float  g_dA [BLQ*NHQ];
__device__ float  g_y  [BLQ*DIQ];
__device__ __half g_yh [BLQ*DIQ];
__device__ __half g_h1 [BLQ*DFFQ];
__device__ float  g_hfin [BQ*NHQ*NCHUNK*HDQ*NSQ];
__device__ float  g_hinit[BQ*NHQ*NCHUNK*HDQ*NSQ];
__device__ float  g_cuma [BLQ*NHQ];
__device__ float  g_P    [BQ*NHQ*NCHUNK];
__device__ __half g_wip[NLAYERSQ*DPROJQ*DMQ];
__device__ __half g_wop[NLAYERSQ*DMQ*DIQ];
__device__ __half g_w1 [NLAYERSQ*DFFQ*DMQ];
__device__ __half g_w2 [NLAYERSQ*DMQ*DFFQ];

// ---------------- helpers ----------------
__device__ __forceinline__ float block_reduce_sum(float v, float* sh) {
    int lane = threadIdx.x & 31, wid = threadIdx.x >> 5;
    #pragma unroll
    for (int o = 16; o; o >>= 1) v += __shfl_xor_sync(0xFFFFFFFFu, v, o);
    if (lane == 0) sh[wid] = v;
    __syncthreads();
    int nw = blockDim.x >> 5;
    v = (threadIdx.x < nw) ? sh[threadIdx.x] : 0.f;
    if (wid == 0) {
        #pragma unroll
        for (int o = 16; o; o >>= 1) v += __shfl_xor_sync(0xFFFFFFFFu, v, o);
        if (lane == 0) sh[0] = v;
    }
    __syncthreads();
    float r = sh[0];
    __syncthreads();
    return r;
}

__device__ __forceinline__ void cp16(uint32_t dst, const void* src, bool pred) {
    int sz = pred ? 16 : 0;
    asm volatile("cp.async.cg.shared.global [%0], [%1], 16, %2;\n"
                 :: "r"(dst), "l"(src), "r"(sz) : "memory");
}
__device__ __forceinline__ void cp_commit() {
    asm volatile("cp.async.commit_group;\n" ::: "memory");
}

__device__ __forceinline__ void ldsm4(uint32_t& r0, uint32_t& r1, uint32_t& r2, uint32_t& r3,
                                      uint32_t addr) {
    asm volatile("ldmatrix.sync.aligned.m8n8.x4.shared.b16 {%0,%1,%2,%3}, [%4];"
                 : "=r"(r0), "=r"(r1), "=r"(r2), "=r"(r3) : "r"(addr));
}

// fused 4-tensor fp16 conversion (grid-stride per segment)
__global__ void cvt4_h_kernel(const float* __restrict__ i0, __half* __restrict__ o0, int n0,
                              const float* __restrict__ i1, __half* __restrict__ o1, int n1,
                              const float* __restrict__ i2, __half* __restrict__ o2, int n2,
                              const float* __restrict__ i3, __half* __restrict__ o3, int n3) {
    int stride4 = gridDim.x * blockDim.x * 4;
    int base = (blockIdx.x * blockDim.x + threadIdx.x) * 4;
    #pragma unroll
    for (int seg = 0; seg < 4; seg++) {
        const float* in = (seg==0) ? i0 : (seg==1) ? i1 : (seg==2) ? i2 : i3;
        __half* out     = (seg==0) ? o0 : (seg==1) ? o1 : (seg==2) ? o2 : o3;
        int n           = (seg==0) ? n0 : (seg==1) ? n1 : (seg==2) ? n2 : n3;
        for (int i = base; i < n; i += stride4) {
            float4 v = *(const float4*)&in[i];
            __half2 h0 = __floats2half2_rn(v.x, v.y);
            __half2 h1 = __floats2half2_rn(v.z, v.w);
            *(__half2*)&out[i]   = h0;
            *(__half2*)&out[i+2] = h1;
        }
    }
}

// ---------------- rmsnorm over DM=512 ----------------
// OUTH: 1 = write fp16 (GEMM operand), 0 = write fp32 (final output)
template<int COPY, int OUTH>
__global__ void rmsnorm_kernel(const float* __restrict__ in, const float* __restrict__ w,
                               void* __restrict__ outv, float* __restrict__ xcopy) {
    __shared__ float sh[32];
    int m = blockIdx.x;
    int t = threadIdx.x;
    const float* row = in + (size_t)m * DMQ;
    float v[4]; float ss = 0.f;
    #pragma unroll
    for (int i = 0; i < 4; i++) { v[i] = row[t + i*128]; ss += v[i]*v[i]; }
    float tot = block_reduce_sum(ss, sh);
    float scale = rsqrtf(tot * (1.f/DMQ) + EPSQ);
    #pragma unroll
    for (int i = 0; i < 4; i++) {
        int c = t + i*128;
        float o = v[i] * scale * w[c];
        if (OUTH) ((__half*)outv)[(size_t)m * DMQ + c] = __float2half(o);
        else      ((float*)outv)[(size_t)m * DMQ + c] = o;
        if (COPY) xcopy[(size_t)m * DMQ + c] = v[i];
    }
}

// ---------------- fp16 tensor-core GEMM: C[M,N] = A[M,K] @ W[N,K]^T (+ epilogue) ----------------
// mma.m16n8k16.f16, cp.async double-buffered, ldmatrix fragment loads.
// 128 threads = 4 warps (2x2), warp tile (BMt/2) x 64. fp32 accumulate.
// EPI: 0 = plain f32 out, 1 = bias+gelu -> fp16 out, 2 = +resid f32, 3 = bias+resid f32
template<int EPI, int BMt>
__global__ void __launch_bounds__(128, (BMt==128) ? 2 : 3)
gemm_h(const __half* __restrict__ A, const __half* __restrict__ W,
       void* __restrict__ Cv, const float* __restrict__ bias,
       const float* __restrict__ resid, int M, int N, int K) {
    constexpr int MT = BMt / 32;
    extern __shared__ __half smh[];
    __half* As = smh;                        // [2][BMt][LDKH]
    __half* Bs = smh + 2 * BMt * LDKH;       // [2][BN][LDKH]

    int tid  = threadIdx.x;
    int warp = tid >> 5, lane = tid & 31;
    int wm = warp & 1;
    int wn = warp >> 1;

    int m0 = blockIdx.y * BMt;
    int n0 = blockIdx.x * BN;

    float acc[MT][8][4];
    #pragma unroll
    for (int i = 0; i < MT; i++)
        #pragma unroll
        for (int j = 0; j < 8; j++)
            #pragma unroll
            for (int c = 0; c < 4; c++) acc[i][j][c] = 0.f;

    // stage one BK=64-half tile of A and B (8 chunks of 16B per row)
    auto stage = [&](int buf, int k0) {
        __half* Ab = As + buf * BMt * LDKH;
        #pragma unroll
        for (int it = 0; it < (BMt*8)/128; it++) {
            int ch = it * 128 + tid;
            int r = ch >> 3, kc = (ch & 7) * 8;
            uint32_t dst = (uint32_t)__cvta_generic_to_shared(&Ab[r * LDKH + kc]);
            cp16(dst, &A[(size_t)(m0 + r) * K + k0 + kc], true);
        }
        __half* Bb = Bs + buf * BN * LDKH;
        #pragma unroll
        for (int it = 0; it < 8; it++) {
            int ch = it * 128 + tid;
            int r = ch >> 3, kc = (ch & 7) * 8;
            int n = n0 + r;
            bool ok = (n < N);
            uint32_t dst = (uint32_t)__cvta_generic_to_shared(&Bb[r * LDKH + kc]);
            cp16(dst, &W[(size_t)(ok ? n : 0) * K + k0 + kc], ok);
        }
        cp_commit();
    };

    // ldmatrix per-lane base offsets (bytes): identical mapping to tf32 layout
    uint32_t aRow = (uint32_t)(wm * (BMt/2) + (lane & 15));
    uint32_t aColB = (lane >> 4) * 16;                 // 0 or 16 bytes (8 halves)
    uint32_t aBaseOff = aRow * (LDKH*2) + aColB;
    uint32_t bRow = (uint32_t)(wn * 64 + (lane & 7) + ((lane & 16) >> 1));
    uint32_t bColB = (lane & 8) * 2;                   // 0 or 16 bytes
    uint32_t bBaseOff = bRow * (LDKH*2) + bColB;

    int ntiles = K / BK;
    stage(0, 0);
    for (int i = 0; i < ntiles; i++) {
        if (i + 1 < ntiles) {
            stage((i + 1) & 1, (i + 1) * BK);
            asm volatile("cp.async.wait_group 1;\n" ::: "memory");
        } else {
            asm volatile("cp.async.wait_group 0;\n" ::: "memory");
        }
        __syncthreads();

        uint32_t sAb = (uint32_t)__cvta_generic_to_shared(As + (i & 1) * BMt * LDKH);
        uint32_t sBb = (uint32_t)__cvta_generic_to_shared(Bs + (i & 1) * BN * LDKH);
        uint32_t aAddr = sAb + aBaseOff;
        uint32_t bAddr = sBb + bBaseOff;

        #pragma unroll
        for (int kk = 0; kk < BK; kk += 16) {          // k16 per mma
            uint32_t af[MT][4];
            #pragma unroll
            for (int mt = 0; mt < MT; mt++)
                ldsm4(af[mt][0], af[mt][1], af[mt][2], af[mt][3],
                      aAddr + (uint32_t)(mt * 16 * LDKH + kk) * 2);
            uint32_t bf[8][2];
            #pragma unroll
            for (int ntp = 0; ntp < 4; ntp++)
                ldsm4(bf[2*ntp][0], bf[2*ntp][1], bf[2*ntp+1][0], bf[2*ntp+1][1],
                      bAddr + (uint32_t)(ntp * 16 * LDKH + kk) * 2);
            #pragma unroll
            for (int mt = 0; mt < MT; mt++)
                #pragma unroll
                for (int nt = 0; nt < 8; nt++) {
                    asm volatile(
                        "mma.sync.aligned.m16n8k16.row.col.f32.f16.f16.f32 "
                        "{%0,%1,%2,%3}, {%4,%5,%6,%7}, {%8,%9}, {%0,%1,%2,%3};"
                        : "+f"(acc[mt][nt][0]), "+f"(acc[mt][nt][1]),
                          "+f"(acc[mt][nt][2]), "+f"(acc[mt][nt][3])
                        : "r"(af[mt][0]), "r"(af[mt][1]), "r"(af[mt][2]), "r"(af[mt][3]),
                          "r"(bf[nt][0]), "r"(bf[nt][1]));
                }
        }
        __syncthreads();
    }

    int gg = lane >> 2, tt = lane & 3;
    #pragma unroll
    for (int mt = 0; mt < MT; mt++) {
        #pragma unroll
        for (int nt = 0; nt < 8; nt++) {
            int mbase = m0 + wm * (BMt/2) + mt * 16 + gg;
            int nn = n0 + wn * 64 + nt * 8 + 2 * tt;
            if (nn < N) {
                #pragma unroll
                for (int rhalf = 0; rhalf < 2; rhalf++) {
                    int mm = mbase + rhalf * 8;
                    float v0 = acc[mt][nt][rhalf*2 + 0];
                    float v1 = acc[mt][nt][rhalf*2 + 1];
                    if (EPI == 1) {
                        v0 += bias[nn];     v1 += bias[nn+1];
                        v0 = 0.5f * v0 * (1.f + erff(v0 * 0.70710678118654752f));
                        v1 = 0.5f * v1 * (1.f + erff(v1 * 0.70710678118654752f));
                        *(__half2*)&((__half*)Cv)[(size_t)mm * N + nn] = __floats2half2_rn(v0, v1);
                    } else if (EPI == 2) {
                        float2 r = *(const float2*)&resid[(size_t)mm * N + nn];
                        *(float2*)&((float*)Cv)[(size_t)mm * N + nn] = make_float2(v0 + r.x, v1 + r.y);
                    } else if (EPI == 3) {
                        float2 r = *(const float2*)&resid[(size_t)mm * N + nn];
                        *(float2*)&((float*)Cv)[(size_t)mm * N + nn] =
                            make_float2(v0 + bias[nn] + r.x, v1 + bias[nn+1] + r.y);
                    } else {
                        *(float2*)&((float*)Cv)[(size_t)mm * N + nn] = make_float2(v0, v1);
                    }
                }
            }
        }
    }
}

// ---------------- prep: bc conv+silu, dt (softplus), dA (exp) ----------------
__global__ void prep_kernel(const float* __restrict__ zx, const float* __restrict__ cw,
                            const float* __restrict__ cb,
                            const float* __restrict__ dtb, const float* __restrict__ Alog,
                            float* __restrict__ bc, float* __restrict__ dt,
                            float* __restrict__ dA) {
    int idx = blockIdx.x * blockDim.x + threadIdx.x;
    if (idx >= BLQ * 48) return;
    int row = idx / 48;
    int j = idx % 48;
    int b = row / LQ, l = row % LQ;
    if (j < 2*NSQ) {
        int ch = DIQ + j;
        int col = DIQ + ch;
        float acc = cb[ch];
        #pragma unroll
        for (int t = 0; t < DCONVQ; t++) {
            int ll = l - (DCONVQ-1) + t;
            if (ll >= 0)
                acc = fmaf(zx[(size_t)(b*LQ + ll)*DPROJQ + col], cw[ch*DCONVQ + t], acc);
        }
        bc[(size_t)row*(2*NSQ) + j] = acc / (1.f + expf(-acc));
    } else {
        int h = j - 2*NSQ;
        float raw = zx[(size_t)row*DPROJQ + (DPROJQ - NHQ) + h] + dtb[h];
        float dtv = (raw > 20.f) ? raw : log1pf(expf(raw));
        dt[(size_t)row*NHQ + h] = dtv;
        dA[(size_t)row*NHQ + h] = expf(-expf(Alog[h]) * dtv);
    }
}

// ---------------- chunked scan pass 1 ----------------
__global__ void scan1_kernel(const float* __restrict__ zx, const float* __restrict__ cw,
                             const float* __restrict__ cb,
                             const float* __restrict__ bcin, const float* __restrict__ dt,
                             const float* __restrict__ dA, const float* __restrict__ D_ssm,
                             float* __restrict__ y, float* __restrict__ hfin,
                             float* __restrict__ cuma, float* __restrict__ P) {
    int blk = blockIdx.x;
    int c = blk % NCHUNK;
    int bh = blk / NCHUNK;
    int h = bh % NHQ, b = bh / NHQ;
    int p = threadIdx.x;
    int lane = p & 31;

    int chx = h * HDQ + p;
    int colx = DIQ + chx;

    float cwx[DCONVQ];
    #pragma unroll
    for (int j = 0; j < DCONVQ; j++) cwx[j] = cw[chx*DCONVQ + j];
    float cbx = cb[chx];
    float Dh = D_ssm[h];

    int l0 = c * CLEN;
    size_t rowbase = (size_t)b * LQ;

    float xw0=0.f, xw1=0.f, xw2=0.f;
    {
        int ll = l0 - 3;
        if (ll >= 0) xw0 = zx[(rowbase + ll)*DPROJQ + colx];
        ll = l0 - 2;
        if (ll >= 0) xw1 = zx[(rowbase + ll)*DPROJQ + colx];
        ll = l0 - 1;
        if (ll >= 0) xw2 = zx[(rowbase + ll)*DPROJQ + colx];
    }

    float hs[NSQ];
    #pragma unroll
    for (int n = 0; n < NSQ; n++) hs[n] = 0.f;
    float cum = 1.f;

    for (int l = l0; l < l0 + CLEN; l++) {
        size_t row = rowbase + l;
        float xn = zx[row*DPROJQ + colx];
        float accx = cbx;
        accx = fmaf(xw0, cwx[0], accx);
        accx = fmaf(xw1, cwx[1], accx);
        accx = fmaf(xw2, cwx[2], accx);
        accx = fmaf(xn,  cwx[3], accx);
        xw0 = xw1; xw1 = xw2; xw2 = xn;

        float xv  = accx / (1.f + expf(-accx));
        float bcv = bcin[row*(2*NSQ) + lane];
        float dtv = dt[row*NHQ + h];
        float a   = dA[row*NHQ + h];
        cum *= a;
        if (p == 0) cuma[row*NHQ + h] = cum;

        float coef = dtv * xv;
        float acc = 0.f;
        #pragma unroll
        for (int n = 0; n < NSQ; n++) {
            float Bn = __shfl_sync(0xFFFFFFFFu, bcv, n);
            float Cn = __shfl_sync(0xFFFFFFFFu, bcv, 16 + n);
            hs[n] = fmaf(hs[n], a, coef * Bn);
            acc = fmaf(hs[n], Cn, acc);
        }
        y[row*DIQ + h*HDQ + p] = acc + Dh * xv;
    }
    size_t base = ((size_t)blk * HDQ + p) * NSQ;
    #pragma unroll
    for (int n = 0; n < NSQ; n++) hfin[base + n] = hs[n];
    if (p == 0) P[blk] = cum;
}

// ---------------- chunked scan pass 2 (4 blocks per bh) ----------------
__global__ void scan2_kernel(const float* __restrict__ hfin, const float* __restrict__ P,
                             float* __restrict__ hinit) {
    int bh = blockIdx.x >> 2;
    int e  = (blockIdx.x & 3) * 256 + threadIdx.x;
    float cur = 0.f;
    #pragma unroll 4
    for (int cc = 0; cc < NCHUNK; cc++) {
        size_t idx = (size_t)(bh * NCHUNK + cc) * (HDQ*NSQ) + e;
        hinit[idx] = cur;
        cur = P[bh * NCHUNK + cc] * cur + hfin[idx];
    }
}

// ---------------- chunked scan pass 3 ----------------
__global__ void scan3_kernel(const float* __restrict__ bc, const float* __restrict__ cuma,
                             const float* __restrict__ hinit, float* __restrict__ y) {
    int blk = blockIdx.x;
    int c = blk % NCHUNK;
    if (c == 0) return;
    int bh = blk / NCHUNK;
    int h = bh % NHQ, b = bh / NHQ;
    int p = threadIdx.x;
    int lane = p & 31;
    float hi[NSQ];
    size_t base = ((size_t)blk * HDQ + p) * NSQ;
    #pragma unroll
    for (int n = 0; n < NSQ; n++) hi[n] = hinit[base + n];
    int l0 = c * CLEN;
    for (int l = l0; l < l0 + CLEN; l++) {
        size_t row = (size_t)b * LQ + l;
        float bcv = bc[row*(2*NSQ) + lane];
        float ca  = cuma[row*NHQ + h];
        float corr = 0.f;
        #pragma unroll
        for (int n = 0; n < NSQ; n++)
            corr = fmaf(hi[n], __shfl_sync(0xFFFFFFFFu, bcv, 16 + n), corr);
        y[row*DIQ + h*HDQ + p] += ca * corr;
    }
}

// ---------------- gated RMSNorm over DI=1024 -> fp16 out ----------------
__global__ void gate_norm_kernel(const float* __restrict__ y, const float* __restrict__ zx,
                                 const float* __restrict__ gw, __half* __restrict__ yh) {
    __shared__ float sh[32];
    int m = blockIdx.x;
    int t = threadIdx.x;
    float v[4]; float ss = 0.f;
    #pragma unroll
    for (int i = 0; i < 4; i++) {
        int c = t + i*256;
        float z = zx[(size_t)m*DPROJQ + c];
        float yy = y[(size_t)m*DIQ + c];
        float g = z / (1.f + expf(-z));
        v[i] = yy * g;
        ss += v[i]*v[i];
    }
    float tot = block_reduce_sum(ss, sh);
    float scale = rsqrtf(tot * (1.f/DIQ) + EPSQ);
    #pragma unroll
    for (int i = 0; i < 4; i++) {
        int c = t + i*256;
        yh[(size_t)m*DIQ + c] = __float2half(v[i] * scale * gw[c]);
    }
}

// ---------------- launcher ----------------
extern "C" void kernel_launch(void* const* d_in, const int* in_sizes, int n_in,
                              void* d_out, int out_size) {
    const float* x          = (const float*)d_in[0];
    const float* in_proj_w  = (const float*)d_in[1];
    const float* conv_w     = (const float*)d_in[2];
    const float* conv_b     = (const float*)d_in[3];
    const float* dt_bias    = (const float*)d_in[4];
    const float* A_log      = (const float*)d_in[5];
    const float* D_ssm      = (const float*)d_in[6];
    const float* gnorm_w    = (const float*)d_in[7];
    const float* out_proj_w = (const float*)d_in[8];
    const float* ffn_w1     = (const float*)d_in[9];
    const float* ffn_b1     = (const float*)d_in[10];
    const float* ffn_w2     = (const float*)d_in[11];
    const float* ffn_b2     = (const float*)d_in[12];
    const float* norm_mamba = (const float*)d_in[13];
    const float* norm_ffn   = (const float*)d_in[14];
    const float* final_norm = (const float*)d_in[15];
    float* out = (float*)d_out;

    float *gx, *gzx, *gbc, *gdt, *gdA, *gy;
    float *ghfin, *ghinit, *gcuma, *gP;
    __half *gxn, *gyh, *gh1, *gwip, *gwop, *gw1, *gw2;
    cudaGetSymbolAddress((void**)&gx,  g_x);
    cudaGetSymbolAddress((void**)&gxn, g_xn);
    cudaGetSymbolAddress((void**)&gzx, g_zx);
    cudaGetSymbolAddress((void**)&gbc, g_bc);
    cudaGetSymbolAddress((void**)&gdt, g_dt);
    cudaGetSymbolAddress((void**)&gdA, g_dA);
    cudaGetSymbolAddress((void**)&gy,  g_y);
    cudaGetSymbolAddress((void**)&gyh, g_yh);
    cudaGetSymbolAddress((void**)&gh1, g_h1);
    cudaGetSymbolAddress((void**)&ghfin, g_hfin);
    cudaGetSymbolAddress((void**)&ghinit,g_hinit);
    cudaGetSymbolAddress((void**)&gcuma, g_cuma);
    cudaGetSymbolAddress((void**)&gP,    g_P);
    cudaGetSymbolAddress((void**)&gwip,  g_wip);
    cudaGetSymbolAddress((void**)&gwop,  g_wop);
    cudaGetSymbolAddress((void**)&gw1,   g_w1);
    cudaGetSymbolAddress((void**)&gw2,   g_w2);

    const int smem128 = (2*128*LDKH + 2*BN*LDKH) * 2;   // bytes (halves)
    const int smem64  = (2*64 *LDKH + 2*BN*LDKH) * 2;
    cudaFuncSetAttribute(gemm_h<0,128>, cudaFuncAttributeMaxDynamicSharedMemorySize, smem128);
    cudaFuncSetAttribute(gemm_h<1,128>, cudaFuncAttributeMaxDynamicSharedMemorySize, smem128);
    cudaFuncSetAttribute(gemm_h<2,64>,  cudaFuncAttributeMaxDynamicSharedMemorySize, smem64);
    cudaFuncSetAttribute(gemm_h<3,64>,  cudaFuncAttributeMaxDynamicSharedMemorySize, smem64);

    // pre-convert all weights to fp16 (one fused launch)
    cvt4_h_kernel<<<2048, 256>>>(
        in_proj_w,  gwip, NLAYERSQ*DPROJQ*DMQ,
        out_proj_w, gwop, NLAYERSQ*DMQ*DIQ,
        ffn_w1,     gw1,  NLAYERSQ*DFFQ*DMQ,
        ffn_w2,     gw2,  NLAYERSQ*DMQ*DFFQ);

    for (int i = 0; i < NLAYERSQ; i++) {
        // --- mamba block ---
        if (i == 0) {
            rmsnorm_kernel<1,1><<<BLQ, 128>>>(x, norm_mamba, gxn, gx);
        } else {
            rmsnorm_kernel<0,1><<<BLQ, 128>>>(gx, norm_mamba + i*DMQ, gxn, nullptr);
        }

        gemm_h<0,128><<<dim3((DPROJQ+BN-1)/BN, BLQ/128), 128, smem128>>>(
            gxn, gwip + (size_t)i*DPROJQ*DMQ, gzx, nullptr, nullptr,
            BLQ, DPROJQ, DMQ);

        prep_kernel<<<(BLQ*48 + 255)/256, 256>>>(
            gzx, conv_w + (size_t)i*CONV_DIMQ*DCONVQ, conv_b + (size_t)i*CONV_DIMQ,
            dt_bias + i*NHQ, A_log + i*NHQ, gbc, gdt, gdA);

        scan1_kernel<<<BQ*NHQ*NCHUNK, HDQ>>>(
            gzx, conv_w + (size_t)i*CONV_DIMQ*DCONVQ, conv_b + (size_t)i*CONV_DIMQ,
            gbc, gdt, gdA, D_ssm + i*NHQ,
            gy, ghfin, gcuma, gP);
        scan2_kernel<<<BQ*NHQ*4, 256>>>(ghfin, gP, ghinit);
        scan3_kernel<<<BQ*NHQ*NCHUNK, HDQ>>>(gbc, gcuma, ghinit, gy);

        gate_norm_kernel<<<BLQ, 256>>>(gy, gzx, gnorm_w + (size_t)i*DIQ, gyh);

        gemm_h<2,64><<<dim3(DMQ/BN, BLQ/64), 128, smem64>>>(
            gyh, gwop + (size_t)i*DMQ*DIQ, gx, nullptr, gx,
            BLQ, DMQ, DIQ);

        // --- ffn block ---
        rmsnorm_kernel<0,1><<<BLQ, 128>>>(gx, norm_ffn + i*DMQ, gxn, nullptr);

        gemm_h<1,128><<<dim3(DFFQ/BN, BLQ/128), 128, smem128>>>(
            gxn, gw1 + (size_t)i*DFFQ*DMQ, gh1, ffn_b1 + (size_t)i*DFFQ, nullptr,
            BLQ, DFFQ, DMQ);

        gemm_h<3,64><<<dim3(DMQ/BN, BLQ/64), 128, smem64>>>(
            gh1, gw2 + (size_t)i*DMQ*DFFQ, gx, ffn_b2 + (size_t)i*DMQ, gx,
            BLQ, DMQ, DFFQ);
    }

    rmsnorm_kernel<0,0><<<BLQ, 128>>>(gx, final_norm, out, nullptr);
}

// round 16
// speedup vs baseline: 1.6095x; 1.0461x over previous
#include <cuda_runtime.h>
#include <cuda_fp16.h>
#include <math.h>
#include <stdint.h>

// ---------------- problem constants ----------------
#define BQ 4
#define LQ 1024
#define DMQ 512
#define DIQ 1024
#define NHQ 16
#define HDQ 64
#define NSQ 16
#define DCONVQ 4
#define CONV_DIMQ 1056
#define DPROJQ 2096
#define DFFQ 2048
#define NLAYERSQ 6
#define BLQ (BQ*LQ)          // 4096 rows
#define EPSQ 1e-5f

// GEMM tiling (fp16): BK=64 halves per tile (128B/row), LDKH=72 (144B stride, conflict-free)
#define BN 128
#define BK 64
#define LDKH 72

// scan chunking
#define NCHUNK 64
#define CLEN (LQ/NCHUNK)     // 16

// ---------------- scratch (device globals, no allocation) ----------------
__device__ float  g_x  [BLQ*DMQ];
__device__ __half g_xn [BLQ*DMQ];
__device__ float  g_zx [BLQ*DPROJQ];
__device__ float  g_bc [BLQ*2*NSQ];
__device__ float  g_dt [BLQ*NHQ];
__device__ float  g_dA [BLQ*NHQ];
__device__ float  g_y  [BLQ*DIQ];
__device__ __half g_yh [BLQ*DIQ];
__device__ __half g_h1 [BLQ*DFFQ];
__device__ float  g_hfin [BQ*NHQ*NCHUNK*HDQ*NSQ];
__device__ float  g_hinit[BQ*NHQ*NCHUNK*HDQ*NSQ];
__device__ float  g_cuma [BLQ*NHQ];
__device__ float  g_P    [BQ*NHQ*NCHUNK];
__device__ __half g_wip[NLAYERSQ*DPROJQ*DMQ];
__device__ __half g_wop[NLAYERSQ*DMQ*DIQ];
__device__ __half g_w1 [NLAYERSQ*DFFQ*DMQ];
__device__ __half g_w2 [NLAYERSQ*DMQ*DFFQ];

// ---------------- helpers ----------------
__device__ __forceinline__ float block_reduce_sum(float v, float* sh) {
    int lane = threadIdx.x & 31, wid = threadIdx.x >> 5;
    #pragma unroll
    for (int o = 16; o; o >>= 1) v += __shfl_xor_sync(0xFFFFFFFFu, v, o);
    if (lane == 0) sh[wid] = v;
    __syncthreads();
    int nw = blockDim.x >> 5;
    v = (threadIdx.x < nw) ? sh[threadIdx.x] : 0.f;
    if (wid == 0) {
        #pragma unroll
        for (int o = 16; o; o >>= 1) v += __shfl_xor_sync(0xFFFFFFFFu, v, o);
        if (lane == 0) sh[0] = v;
    }
    __syncthreads();
    float r = sh[0];
    __syncthreads();
    return r;
}

__device__ __forceinline__ void cp16(uint32_t dst, const void* src, bool pred) {
    int sz = pred ? 16 : 0;
    asm volatile("cp.async.cg.shared.global [%0], [%1], 16, %2;\n"
                 :: "r"(dst), "l"(src), "r"(sz) : "memory");
}
__device__ __forceinline__ void cp_commit() {
    asm volatile("cp.async.commit_group;\n" ::: "memory");
}

__device__ __forceinline__ void ldsm4(uint32_t& r0, uint32_t& r1, uint32_t& r2, uint32_t& r3,
                                      uint32_t addr) {
    asm volatile("ldmatrix.sync.aligned.m8n8.x4.shared.b16 {%0,%1,%2,%3}, [%4];"
                 : "=r"(r0), "=r"(r1), "=r"(r2), "=r"(r3) : "r"(addr));
}

// fused 4-tensor fp16 conversion (grid-stride per segment)
__global__ void cvt4_h_kernel(const float* __restrict__ i0, __half* __restrict__ o0, int n0,
                              const float* __restrict__ i1, __half* __restrict__ o1, int n1,
                              const float* __restrict__ i2, __half* __restrict__ o2, int n2,
                              const float* __restrict__ i3, __half* __restrict__ o3, int n3) {
    int stride4 = gridDim.x * blockDim.x * 4;
    int base = (blockIdx.x * blockDim.x + threadIdx.x) * 4;
    #pragma unroll
    for (int seg = 0; seg < 4; seg++) {
        const float* in = (seg==0) ? i0 : (seg==1) ? i1 : (seg==2) ? i2 : i3;
        __half* out     = (seg==0) ? o0 : (seg==1) ? o1 : (seg==2) ? o2 : o3;
        int n           = (seg==0) ? n0 : (seg==1) ? n1 : (seg==2) ? n2 : n3;
        for (int i = base; i < n; i += stride4) {
            float4 v = *(const float4*)&in[i];
            __half2 h0 = __floats2half2_rn(v.x, v.y);
            __half2 h1 = __floats2half2_rn(v.z, v.w);
            *(__half2*)&out[i]   = h0;
            *(__half2*)&out[i+2] = h1;
        }
    }
}

// ---------------- rmsnorm over DM=512 ----------------
template<int COPY, int OUTH>
__global__ void rmsnorm_kernel(const float* __restrict__ in, const float* __restrict__ w,
                               void* __restrict__ outv, float* __restrict__ xcopy) {
    __shared__ float sh[32];
    int m = blockIdx.x;
    int t = threadIdx.x;
    const float* row = in + (size_t)m * DMQ;
    float v[4]; float ss = 0.f;
    #pragma unroll
    for (int i = 0; i < 4; i++) { v[i] = row[t + i*128]; ss += v[i]*v[i]; }
    float tot = block_reduce_sum(ss, sh);
    float scale = rsqrtf(tot * (1.f/DMQ) + EPSQ);
    #pragma unroll
    for (int i = 0; i < 4; i++) {
        int c = t + i*128;
        float o = v[i] * scale * w[c];
        if (OUTH) ((__half*)outv)[(size_t)m * DMQ + c] = __float2half(o);
        else      ((float*)outv)[(size_t)m * DMQ + c] = o;
        if (COPY) xcopy[(size_t)m * DMQ + c] = v[i];
    }
}

// ---------------- fp16 tensor-core GEMM ----------------
template<int EPI, int BMt>
__global__ void __launch_bounds__(128, (BMt==128) ? 2 : 3)
gemm_h(const __half* __restrict__ A, const __half* __restrict__ W,
       void* __restrict__ Cv, const float* __restrict__ bias,
       const float* __restrict__ resid, int M, int N, int K) {
    constexpr int MT = BMt / 32;
    extern __shared__ __half smh[];
    __half* As = smh;                        // [2][BMt][LDKH]
    __half* Bs = smh + 2 * BMt * LDKH;       // [2][BN][LDKH]

    int tid  = threadIdx.x;
    int warp = tid >> 5, lane = tid & 31;
    int wm = warp & 1;
    int wn = warp >> 1;

    int m0 = blockIdx.y * BMt;
    int n0 = blockIdx.x * BN;

    float acc[MT][8][4];
    #pragma unroll
    for (int i = 0; i < MT; i++)
        #pragma unroll
        for (int j = 0; j < 8; j++)
            #pragma unroll
            for (int c = 0; c < 4; c++) acc[i][j][c] = 0.f;

    auto stage = [&](int buf, int k0) {
        __half* Ab = As + buf * BMt * LDKH;
        #pragma unroll
        for (int it = 0; it < (BMt*8)/128; it++) {
            int ch = it * 128 + tid;
            int r = ch >> 3, kc = (ch & 7) * 8;
            uint32_t dst = (uint32_t)__cvta_generic_to_shared(&Ab[r * LDKH + kc]);
            cp16(dst, &A[(size_t)(m0 + r) * K + k0 + kc], true);
        }
        __half* Bb = Bs + buf * BN * LDKH;
        #pragma unroll
        for (int it = 0; it < 8; it++) {
            int ch = it * 128 + tid;
            int r = ch >> 3, kc = (ch & 7) * 8;
            int n = n0 + r;
            bool ok = (n < N);
            uint32_t dst = (uint32_t)__cvta_generic_to_shared(&Bb[r * LDKH + kc]);
            cp16(dst, &W[(size_t)(ok ? n : 0) * K + k0 + kc], ok);
        }
        cp_commit();
    };

    uint32_t aRow = (uint32_t)(wm * (BMt/2) + (lane & 15));
    uint32_t aColB = (lane >> 4) * 16;
    uint32_t aBaseOff = aRow * (LDKH*2) + aColB;
    uint32_t bRow = (uint32_t)(wn * 64 + (lane & 7) + ((lane & 16) >> 1));
    uint32_t bColB = (lane & 8) * 2;
    uint32_t bBaseOff = bRow * (LDKH*2) + bColB;

    int ntiles = K / BK;
    stage(0, 0);
    for (int i = 0; i < ntiles; i++) {
        if (i + 1 < ntiles) {
            stage((i + 1) & 1, (i + 1) * BK);
            asm volatile("cp.async.wait_group 1;\n" ::: "memory");
        } else {
            asm volatile("cp.async.wait_group 0;\n" ::: "memory");
        }
        __syncthreads();

        uint32_t sAb = (uint32_t)__cvta_generic_to_shared(As + (i & 1) * BMt * LDKH);
        uint32_t sBb = (uint32_t)__cvta_generic_to_shared(Bs + (i & 1) * BN * LDKH);
        uint32_t aAddr = sAb + aBaseOff;
        uint32_t bAddr = sBb + bBaseOff;

        #pragma unroll
        for (int kk = 0; kk < BK; kk += 16) {
            uint32_t af[MT][4];
            #pragma unroll
            for (int mt = 0; mt < MT; mt++)
                ldsm4(af[mt][0], af[mt][1], af[mt][2], af[mt][3],
                      aAddr + (uint32_t)(mt * 16 * LDKH + kk) * 2);
            uint32_t bf[8][2];
            #pragma unroll
            for (int ntp = 0; ntp < 4; ntp++)
                ldsm4(bf[2*ntp][0], bf[2*ntp][1], bf[2*ntp+1][0], bf[2*ntp+1][1],
                      bAddr + (uint32_t)(ntp * 16 * LDKH + kk) * 2);
            #pragma unroll
            for (int mt = 0; mt < MT; mt++)
                #pragma unroll
                for (int nt = 0; nt < 8; nt++) {
                    asm volatile(
                        "mma.sync.aligned.m16n8k16.row.col.f32.f16.f16.f32 "
                        "{%0,%1,%2,%3}, {%4,%5,%6,%7}, {%8,%9}, {%0,%1,%2,%3};"
                        : "+f"(acc[mt][nt][0]), "+f"(acc[mt][nt][1]),
                          "+f"(acc[mt][nt][2]), "+f"(acc[mt][nt][3])
                        : "r"(af[mt][0]), "r"(af[mt][1]), "r"(af[mt][2]), "r"(af[mt][3]),
                          "r"(bf[nt][0]), "r"(bf[nt][1]));
                }
        }
        __syncthreads();
    }

    int gg = lane >> 2, tt = lane & 3;
    #pragma unroll
    for (int mt = 0; mt < MT; mt++) {
        #pragma unroll
        for (int nt = 0; nt < 8; nt++) {
            int mbase = m0 + wm * (BMt/2) + mt * 16 + gg;
            int nn = n0 + wn * 64 + nt * 8 + 2 * tt;
            if (nn < N) {
                #pragma unroll
                for (int rhalf = 0; rhalf < 2; rhalf++) {
                    int mm = mbase + rhalf * 8;
                    float v0 = acc[mt][nt][rhalf*2 + 0];
                    float v1 = acc[mt][nt][rhalf*2 + 1];
                    if (EPI == 1) {
                        v0 += bias[nn];     v1 += bias[nn+1];
                        v0 = 0.5f * v0 * (1.f + erff(v0 * 0.70710678118654752f));
                        v1 = 0.5f * v1 * (1.f + erff(v1 * 0.70710678118654752f));
                        *(__half2*)&((__half*)Cv)[(size_t)mm * N + nn] = __floats2half2_rn(v0, v1);
                    } else if (EPI == 2) {
                        float2 r = *(const float2*)&resid[(size_t)mm * N + nn];
                        *(float2*)&((float*)Cv)[(size_t)mm * N + nn] = make_float2(v0 + r.x, v1 + r.y);
                    } else if (EPI == 3) {
                        float2 r = *(const float2*)&resid[(size_t)mm * N + nn];
                        *(float2*)&((float*)Cv)[(size_t)mm * N + nn] =
                            make_float2(v0 + bias[nn] + r.x, v1 + bias[nn+1] + r.y);
                    } else {
                        *(float2*)&((float*)Cv)[(size_t)mm * N + nn] = make_float2(v0, v1);
                    }
                }
            }
        }
    }
}

// ---------------- prep: bc conv+silu, dt (softplus), dA (exp) ----------------
__global__ void prep_kernel(const float* __restrict__ zx, const float* __restrict__ cw,
                            const float* __restrict__ cb,
                            const float* __restrict__ dtb, const float* __restrict__ Alog,
                            float* __restrict__ bc, float* __restrict__ dt,
                            float* __restrict__ dA) {
    int idx = blockIdx.x * blockDim.x + threadIdx.x;
    if (idx >= BLQ * 48) return;
    int row = idx / 48;
    int j = idx % 48;
    int b = row / LQ, l = row % LQ;
    if (j < 2*NSQ) {
        int ch = DIQ + j;
        int col = DIQ + ch;
        float acc = cb[ch];
        #pragma unroll
        for (int t = 0; t < DCONVQ; t++) {
            int ll = l - (DCONVQ-1) + t;
            if (ll >= 0)
                acc = fmaf(zx[(size_t)(b*LQ + ll)*DPROJQ + col], cw[ch*DCONVQ + t], acc);
        }
        bc[(size_t)row*(2*NSQ) + j] = acc / (1.f + expf(-acc));
    } else {
        int h = j - 2*NSQ;
        float raw = zx[(size_t)row*DPROJQ + (DPROJQ - NHQ) + h] + dtb[h];
        float dtv = (raw > 20.f) ? raw : log1pf(expf(raw));
        dt[(size_t)row*NHQ + h] = dtv;
        dA[(size_t)row*NHQ + h] = expf(-expf(Alog[h]) * dtv);
    }
}

// ---------------- chunked scan pass 1 (bc staged in smem, no shfl) ----------------
__global__ void scan1_kernel(const float* __restrict__ zx, const float* __restrict__ cw,
                             const float* __restrict__ cb,
                             const float* __restrict__ bcin, const float* __restrict__ dt,
                             const float* __restrict__ dA, const float* __restrict__ D_ssm,
                             float* __restrict__ y, float* __restrict__ hfin,
                             float* __restrict__ cuma, float* __restrict__ P) {
    __shared__ float sbc[CLEN][2*NSQ];   // 16 x 32 floats = 2KB
    int blk = blockIdx.x;
    int c = blk % NCHUNK;
    int bh = blk / NCHUNK;
    int h = bh % NHQ, b = bh / NHQ;
    int p = threadIdx.x;

    int chx = h * HDQ + p;
    int colx = DIQ + chx;

    float cwx[DCONVQ];
    #pragma unroll
    for (int j = 0; j < DCONVQ; j++) cwx[j] = cw[chx*DCONVQ + j];
    float cbx = cb[chx];
    float Dh = D_ssm[h];

    int l0 = c * CLEN;
    size_t rowbase = (size_t)b * LQ;

    // stage this chunk's bc rows (coalesced)
    #pragma unroll
    for (int it = 0; it < (CLEN*2*NSQ)/HDQ; it++) {
        int t = it * HDQ + p;
        sbc[t >> 5][t & 31] = bcin[(rowbase + l0 + (t >> 5)) * (2*NSQ) + (t & 31)];
    }
    __syncthreads();

    float xw0=0.f, xw1=0.f, xw2=0.f;
    {
        int ll = l0 - 3;
        if (ll >= 0) xw0 = zx[(rowbase + ll)*DPROJQ + colx];
        ll = l0 - 2;
        if (ll >= 0) xw1 = zx[(rowbase + ll)*DPROJQ + colx];
        ll = l0 - 1;
        if (ll >= 0) xw2 = zx[(rowbase + ll)*DPROJQ + colx];
    }

    float hs[NSQ];
    #pragma unroll
    for (int n = 0; n < NSQ; n++) hs[n] = 0.f;
    float cum = 1.f;

    #pragma unroll 4
    for (int li = 0; li < CLEN; li++) {
        size_t row = rowbase + l0 + li;
        float xn = zx[row*DPROJQ + colx];
        float accx = cbx;
        accx = fmaf(xw0, cwx[0], accx);
        accx = fmaf(xw1, cwx[1], accx);
        accx = fmaf(xw2, cwx[2], accx);
        accx = fmaf(xn,  cwx[3], accx);
        xw0 = xw1; xw1 = xw2; xw2 = xn;

        float xv  = accx / (1.f + expf(-accx));
        float dtv = dt[row*NHQ + h];
        float a   = dA[row*NHQ + h];
        cum *= a;
        if (p == 0) cuma[row*NHQ + h] = cum;

        float coef = dtv * xv;
        float acc = 0.f;
        const float* bcrow = &sbc[li][0];
        #pragma unroll
        for (int n = 0; n < NSQ; n++) {
            hs[n] = fmaf(hs[n], a, coef * bcrow[n]);
            acc = fmaf(hs[n], bcrow[NSQ + n], acc);
        }
        y[row*DIQ + h*HDQ + p] = acc + Dh * xv;
    }
    size_t base = ((size_t)blk * HDQ + p) * NSQ;
    #pragma unroll
    for (int n = 0; n < NSQ; n++) hfin[base + n] = hs[n];
    if (p == 0) P[blk] = cum;
}

// ---------------- chunked scan pass 2 (4 blocks per bh) ----------------
__global__ void scan2_kernel(const float* __restrict__ hfin, const float* __restrict__ P,
                             float* __restrict__ hinit) {
    int bh = blockIdx.x >> 2;
    int e  = (blockIdx.x & 3) * 256 + threadIdx.x;
    float cur = 0.f;
    #pragma unroll 4
    for (int cc = 0; cc < NCHUNK; cc++) {
        size_t idx = (size_t)(bh * NCHUNK + cc) * (HDQ*NSQ) + e;
        hinit[idx] = cur;
        cur = P[bh * NCHUNK + cc] * cur + hfin[idx];
    }
}

// ---------------- chunked scan pass 3 (C + cuma staged in smem, no shfl) ----------------
__global__ void scan3_kernel(const float* __restrict__ bc, const float* __restrict__ cuma,
                             const float* __restrict__ hinit, float* __restrict__ y) {
    __shared__ float sC[CLEN][NSQ];
    __shared__ float sca[CLEN];
    int blk = blockIdx.x;
    int c = blk % NCHUNK;
    if (c == 0) return;
    int bh = blk / NCHUNK;
    int h = bh % NHQ, b = bh / NHQ;
    int p = threadIdx.x;
    int l0 = c * CLEN;
    size_t rowbase = (size_t)b * LQ;

    // stage C columns + cuma for this chunk
    #pragma unroll
    for (int it = 0; it < (CLEN*NSQ)/HDQ; it++) {
        int t = it * HDQ + p;
        sC[t >> 4][t & 15] = bc[(rowbase + l0 + (t >> 4)) * (2*NSQ) + NSQ + (t & 15)];
    }
    if (p < CLEN) sca[p] = cuma[(rowbase + l0 + p)*NHQ + h];
    __syncthreads();

    float hi[NSQ];
    size_t base = ((size_t)blk * HDQ + p) * NSQ;
    #pragma unroll
    for (int n = 0; n < NSQ; n++) hi[n] = hinit[base + n];

    #pragma unroll 4
    for (int li = 0; li < CLEN; li++) {
        size_t row = rowbase + l0 + li;
        float corr = 0.f;
        #pragma unroll
        for (int n = 0; n < NSQ; n++)
            corr = fmaf(hi[n], sC[li][n], corr);
        y[row*DIQ + h*HDQ + p] += sca[li] * corr;
    }
}

// ---------------- gated RMSNorm over DI=1024 -> fp16 out ----------------
__global__ void gate_norm_kernel(const float* __restrict__ y, const float* __restrict__ zx,
                                 const float* __restrict__ gw, __half* __restrict__ yh) {
    __shared__ float sh[32];
    int m = blockIdx.x;
    int t = threadIdx.x;
    float v[4]; float ss = 0.f;
    #pragma unroll
    for (int i = 0; i < 4; i++) {
        int c = t + i*256;
        float z = zx[(size_t)m*DPROJQ + c];
        float yy = y[(size_t)m*DIQ + c];
        float g = z / (1.f + expf(-z));
        v[i] = yy * g;
        ss += v[i]*v[i];
    }
    float tot = block_reduce_sum(ss, sh);
    float scale = rsqrtf(tot * (1.f/DIQ) + EPSQ);
    #pragma unroll
    for (int i = 0; i < 4; i++) {
        int c = t + i*256;
        yh[(size_t)m*DIQ + c] = __float2half(v[i] * scale * gw[c]);
    }
}

// ---------------- launcher ----------------
extern "C" void kernel_launch(void* const* d_in, const int* in_sizes, int n_in,
                              void* d_out, int out_size) {
    const float* x          = (const float*)d_in[0];
    const float* in_proj_w  = (const float*)d_in[1];
    const float* conv_w     = (const float*)d_in[2];
    const float* conv_b     = (const float*)d_in[3];
    const float* dt_bias    = (const float*)d_in[4];
    const float* A_log      = (const float*)d_in[5];
    const float* D_ssm      = (const float*)d_in[6];
    const float* gnorm_w    = (const float*)d_in[7];
    const float* out_proj_w = (const float*)d_in[8];
    const float* ffn_w1     = (const float*)d_in[9];
    const float* ffn_b1     = (const float*)d_in[10];
    const float* ffn_w2     = (const float*)d_in[11];
    const float* ffn_b2     = (const float*)d_in[12];
    const float* norm_mamba = (const float*)d_in[13];
    const float* norm_ffn   = (const float*)d_in[14];
    const float* final_norm = (const float*)d_in[15];
    float* out = (float*)d_out;

    float *gx, *gzx, *gbc, *gdt, *gdA, *gy;
    float *ghfin, *ghinit, *gcuma, *gP;
    __half *gxn, *gyh, *gh1, *gwip, *gwop, *gw1, *gw2;
    cudaGetSymbolAddress((void**)&gx,  g_x);
    cudaGetSymbolAddress((void**)&gxn, g_xn);
    cudaGetSymbolAddress((void**)&gzx, g_zx);
    cudaGetSymbolAddress((void**)&gbc, g_bc);
    cudaGetSymbolAddress((void**)&gdt, g_dt);
    cudaGetSymbolAddress((void**)&gdA, g_dA);
    cudaGetSymbolAddress((void**)&gy,  g_y);
    cudaGetSymbolAddress((void**)&gyh, g_yh);
    cudaGetSymbolAddress((void**)&gh1, g_h1);
    cudaGetSymbolAddress((void**)&ghfin, g_hfin);
    cudaGetSymbolAddress((void**)&ghinit,g_hinit);
    cudaGetSymbolAddress((void**)&gcuma, g_cuma);
    cudaGetSymbolAddress((void**)&gP,    g_P);
    cudaGetSymbolAddress((void**)&gwip,  g_wip);
    cudaGetSymbolAddress((void**)&gwop,  g_wop);
    cudaGetSymbolAddress((void**)&gw1,   g_w1);
    cudaGetSymbolAddress((void**)&gw2,   g_w2);

    const int smem128 = (2*128*LDKH + 2*BN*LDKH) * 2;
    const int smem64  = (2*64 *LDKH + 2*BN*LDKH) * 2;
    cudaFuncSetAttribute(gemm_h<0,128>, cudaFuncAttributeMaxDynamicSharedMemorySize, smem128);
    cudaFuncSetAttribute(gemm_h<1,128>, cudaFuncAttributeMaxDynamicSharedMemorySize, smem128);
    cudaFuncSetAttribute(gemm_h<2,64>,  cudaFuncAttributeMaxDynamicSharedMemorySize, smem64);
    cudaFuncSetAttribute(gemm_h<3,64>,  cudaFuncAttributeMaxDynamicSharedMemorySize, smem64);

    cvt4_h_kernel<<<2048, 256>>>(
        in_proj_w,  gwip, NLAYERSQ*DPROJQ*DMQ,
        out_proj_w, gwop, NLAYERSQ*DMQ*DIQ,
        ffn_w1,     gw1,  NLAYERSQ*DFFQ*DMQ,
        ffn_w2,     gw2,  NLAYERSQ*DMQ*DFFQ);

    for (int i = 0; i < NLAYERSQ; i++) {
        // --- mamba block ---
        if (i == 0) {
            rmsnorm_kernel<1,1><<<BLQ, 128>>>(x, norm_mamba, gxn, gx);
        } else {
            rmsnorm_kernel<0,1><<<BLQ, 128>>>(gx, norm_mamba + i*DMQ, gxn, nullptr);
        }

        gemm_h<0,128><<<dim3((DPROJQ+BN-1)/BN, BLQ/128), 128, smem128>>>(
            gxn, gwip + (size_t)i*DPROJQ*DMQ, gzx, nullptr, nullptr,
            BLQ, DPROJQ, DMQ);

        prep_kernel<<<(BLQ*48 + 255)/256, 256>>>(
            gzx, conv_w + (size_t)i*CONV_DIMQ*DCONVQ, conv_b + (size_t)i*CONV_DIMQ,
            dt_bias + i*NHQ, A_log + i*NHQ, gbc, gdt, gdA);

        scan1_kernel<<<BQ*NHQ*NCHUNK, HDQ>>>(
            gzx, conv_w + (size_t)i*CONV_DIMQ*DCONVQ, conv_b + (size_t)i*CONV_DIMQ,
            gbc, gdt, gdA, D_ssm + i*NHQ,
            gy, ghfin, gcuma, gP);
        scan2_kernel<<<BQ*NHQ*4, 256>>>(ghfin, gP, ghinit);
        scan3_kernel<<<BQ*NHQ*NCHUNK, HDQ>>>(gbc, gcuma, ghinit, gy);

        gate_norm_kernel<<<BLQ, 256>>>(gy, gzx, gnorm_w + (size_t)i*DIQ, gyh);

        gemm_h<2,64><<<dim3(DMQ/BN, BLQ/64), 128, smem64>>>(
            gyh, gwop + (size_t)i*DMQ*DIQ, gx, nullptr, gx,
            BLQ, DMQ, DIQ);

        // --- ffn block ---
        rmsnorm_kernel<0,1><<<BLQ, 128>>>(gx, norm_ffn + i*DMQ, gxn, nullptr);

        gemm_h<1,128><<<dim3(DFFQ/BN, BLQ/128), 128, smem128>>>(
            gxn, gw1 + (size_t)i*DFFQ*DMQ, gh1, ffn_b1 + (size_t)i*DFFQ, nullptr,
            BLQ, DFFQ, DMQ);

        gemm_h<3,64><<<dim3(DMQ/BN, BLQ/64), 128, smem64>>>(
            gh1, gw2 + (size_t)i*DMQ*DFFQ, gx, ffn_b2 + (size_t)i*DMQ, gx,
            BLQ, DMQ, DFFQ);
    }

    rmsnorm_kernel<0,0><<<BLQ, 128>>>(gx, final_norm, out, nullptr);
}